// round 3
// baseline (speedup 1.0000x reference)
#include <cuda_runtime.h>
#include <math.h>

#define NUM_B 2
#define NUM_N 2048
#define NUM_C 1024
#define NUM_H 16
#define HD    64
#define MTOT  (NUM_B*NUM_N)      /* 4096 */

// Scratch (allocation-free: __device__ globals)
__device__ float g_q[NUM_B*NUM_H*NUM_N*HD];   // 16 MB
__device__ float g_k[NUM_B*NUM_H*NUM_N*HD];
__device__ float g_v[NUM_B*NUM_H*NUM_N*HD];
__device__ float g_ao[NUM_B*NUM_N*NUM_C];     // attention out, [B,N,C]

// ---------------------------------------------------------------------------
// Kernel 1: QKV GEMM.  out[m,n] = sum_k x[m,k] * w_qkv[n,k]   (NT)
// M=4096, N=3072, K=1024.  BM=BN=128, BK=16, 256 thr, 8x8/thread (4+4 split).
// Epilogue scatters into g_q/g_k/g_v laid out [B,H,N,d].
// ---------------------------------------------------------------------------
__global__ __launch_bounds__(256) void qkv_gemm(const float* __restrict__ A,
                                                const float* __restrict__ W) {
    __shared__ float As[16][128];
    __shared__ float Bs[16][128];
    const int tid = threadIdx.x;
    const int bm = blockIdx.y * 128;
    const int bn = blockIdx.x * 128;
    const int tx = tid & 15, ty = tid >> 4;
    const int lr = tid >> 2;          // 0..63
    const int lc = (tid & 3) * 4;     // 0,4,8,12

    float acc[8][8] = {};

    for (int k0 = 0; k0 < NUM_C; k0 += 16) {
#pragma unroll
        for (int i = 0; i < 2; i++) {
            float4 a4 = *reinterpret_cast<const float4*>(&A[(size_t)(bm + lr + i*64)*NUM_C + k0 + lc]);
            As[lc+0][lr+i*64] = a4.x; As[lc+1][lr+i*64] = a4.y;
            As[lc+2][lr+i*64] = a4.z; As[lc+3][lr+i*64] = a4.w;
            float4 b4 = *reinterpret_cast<const float4*>(&W[(size_t)(bn + lr + i*64)*NUM_C + k0 + lc]);
            Bs[lc+0][lr+i*64] = b4.x; Bs[lc+1][lr+i*64] = b4.y;
            Bs[lc+2][lr+i*64] = b4.z; Bs[lc+3][lr+i*64] = b4.w;
        }
        __syncthreads();
#pragma unroll
        for (int k = 0; k < 16; k++) {
            float ra[8], rb[8];
            *reinterpret_cast<float4*>(&ra[0]) = *reinterpret_cast<const float4*>(&As[k][ty*4]);
            *reinterpret_cast<float4*>(&ra[4]) = *reinterpret_cast<const float4*>(&As[k][64+ty*4]);
            *reinterpret_cast<float4*>(&rb[0]) = *reinterpret_cast<const float4*>(&Bs[k][tx*4]);
            *reinterpret_cast<float4*>(&rb[4]) = *reinterpret_cast<const float4*>(&Bs[k][64+tx*4]);
#pragma unroll
            for (int i = 0; i < 8; i++)
#pragma unroll
                for (int j = 0; j < 8; j++)
                    acc[i][j] = fmaf(ra[i], rb[j], acc[i][j]);
        }
        __syncthreads();
    }

    // Epilogue: which tensor (q/k/v) is constant per block (bn range < 1024 each)
    const int which = bn >> 10;
    float* dst = (which == 0) ? g_q : ((which == 1) ? g_k : g_v);
#pragma unroll
    for (int ih = 0; ih < 2; ih++) {
#pragma unroll
        for (int i = 0; i < 4; i++) {
            int m   = bm + ih*64 + ty*4 + i;
            int b   = m >> 11;
            int tok = m & 2047;
#pragma unroll
            for (int jh = 0; jh < 2; jh++) {
                int n  = bn + jh*64 + tx*4;
                int c  = n & 1023;
                int h  = c >> 6;
                int d0 = c & 63;
                float4 v4 = make_float4(acc[ih*4+i][jh*4+0], acc[ih*4+i][jh*4+1],
                                        acc[ih*4+i][jh*4+2], acc[ih*4+i][jh*4+3]);
                *reinterpret_cast<float4*>(
                    &dst[(((size_t)(b*NUM_H + h))*NUM_N + tok)*HD + d0]) = v4;
            }
        }
    }
}

// ---------------------------------------------------------------------------
// Kernel 2: LayerNorm over last dim (d=64). One warp per row, 2 elems/lane.
// ---------------------------------------------------------------------------
__global__ __launch_bounds__(256) void ln_kernel(float* __restrict__ t,
                                                 const float* __restrict__ gamma,
                                                 const float* __restrict__ beta) {
    int row  = blockIdx.x * 8 + (threadIdx.x >> 5);
    int lane = threadIdx.x & 31;
    float2 v = *reinterpret_cast<float2*>(&t[(size_t)row*HD + lane*2]);
    float s  = v.x + v.y;
    float ss = v.x*v.x + v.y*v.y;
#pragma unroll
    for (int o = 16; o > 0; o >>= 1) {
        s  += __shfl_xor_sync(0xffffffffu, s,  o);
        ss += __shfl_xor_sync(0xffffffffu, ss, o);
    }
    float mu  = s * (1.0f/64.0f);
    float var = ss * (1.0f/64.0f) - mu*mu;
    float inv = rsqrtf(var + 1e-5f);
    float g0 = gamma[lane*2],   g1 = gamma[lane*2+1];
    float b0 = beta[lane*2],    b1 = beta[lane*2+1];
    v.x = (v.x - mu)*inv*g0 + b0;
    v.y = (v.y - mu)*inv*g1 + b1;
    *reinterpret_cast<float2*>(&t[(size_t)row*HD + lane*2]) = v;
}

// ---------------------------------------------------------------------------
// Kernel 3: flash attention fp32. Block = 64 queries of one (b,h).
// 256 thr, 16x16 grid, 4x4 microtile. Online softmax. smem = 48KB exactly.
// ---------------------------------------------------------------------------
__global__ __launch_bounds__(256) void attn_kernel(const unsigned char* __restrict__ mask) {
    __shared__ float Qs[64][64];   // transposed: Qs[d][q], pre-scaled
    __shared__ float KVs[64][64];  // K phase: transposed [d][k]; V phase: natural [k][d]
    __shared__ float Ps[64][64];   // natural [q][k]

    const int bh = blockIdx.y;            // b*16 + h
    const int b  = bh >> 4;
    const int h  = bh & 15;
    const int q0 = blockIdx.x * 64;

    const float* Qp = g_q + ((size_t)bh*NUM_N + q0)*HD;
    const float* Kp = g_k + (size_t)bh*NUM_N*HD;
    const float* Vp = g_v + (size_t)bh*NUM_N*HD;
    const unsigned char* mp = mask + (size_t)b*NUM_N*NUM_N + (size_t)q0*NUM_N;

    const int tid = threadIdx.x;
    const int tx = tid & 15, ty = tid >> 4;

    // Load Q transposed + fold in 1/sqrt(d) scale
#pragma unroll
    for (int r0 = 0; r0 < 64; r0 += 16) {
        int r = r0 + ty;
        int c = tx * 4;
        float4 v = *reinterpret_cast<const float4*>(&Qp[(size_t)r*HD + c]);
        Qs[c+0][r] = v.x * 0.125f;  Qs[c+1][r] = v.y * 0.125f;
        Qs[c+2][r] = v.z * 0.125f;  Qs[c+3][r] = v.w * 0.125f;
    }

    float m_i[4], l_i[4], O[4][4];
#pragma unroll
    for (int i = 0; i < 4; i++) {
        m_i[i] = -3.402823466e38f; l_i[i] = 0.0f;
#pragma unroll
        for (int j = 0; j < 4; j++) O[i][j] = 0.0f;
    }

    for (int kt = 0; kt < NUM_N/64; kt++) {
        const int k0 = kt * 64;
        __syncthreads();   // prior O-gemm done (and Qs visible on iter 0)
        // load K transposed
#pragma unroll
        for (int r0 = 0; r0 < 64; r0 += 16) {
            int r = r0 + ty;
            int c = tx * 4;
            float4 v = *reinterpret_cast<const float4*>(&Kp[(size_t)(k0+r)*HD + c]);
            KVs[c+0][r] = v.x; KVs[c+1][r] = v.y; KVs[c+2][r] = v.z; KVs[c+3][r] = v.w;
        }
        __syncthreads();

        // S = Q * K^T (tile 64x64x64)
        float S[4][4] = {};
#pragma unroll
        for (int dd = 0; dd < 64; dd++) {
            float4 qa = *reinterpret_cast<const float4*>(&Qs[dd][ty*4]);
            float4 kb = *reinterpret_cast<const float4*>(&KVs[dd][tx*4]);
            float ra[4] = {qa.x, qa.y, qa.z, qa.w};
            float rb[4] = {kb.x, kb.y, kb.z, kb.w};
#pragma unroll
            for (int i = 0; i < 4; i++)
#pragma unroll
                for (int j = 0; j < 4; j++)
                    S[i][j] = fmaf(ra[i], rb[j], S[i][j]);
        }

        // mask
#pragma unroll
        for (int i = 0; i < 4; i++) {
            uchar4 mv = *reinterpret_cast<const uchar4*>(
                &mp[(size_t)(ty*4+i)*NUM_N + k0 + tx*4]);
            if (mv.x) S[i][0] = -3.402823466e38f;
            if (mv.y) S[i][1] = -3.402823466e38f;
            if (mv.z) S[i][2] = -3.402823466e38f;
            if (mv.w) S[i][3] = -3.402823466e38f;
        }

        // online softmax update
#pragma unroll
        for (int i = 0; i < 4; i++) {
            float rmax = fmaxf(fmaxf(S[i][0], S[i][1]), fmaxf(S[i][2], S[i][3]));
#pragma unroll
            for (int o = 1; o < 16; o <<= 1)
                rmax = fmaxf(rmax, __shfl_xor_sync(0xffffffffu, rmax, o));
            float mnew  = fmaxf(m_i[i], rmax);
            float alpha = __expf(m_i[i] - mnew);
            float psum = 0.0f;
#pragma unroll
            for (int j = 0; j < 4; j++) {
                S[i][j] = __expf(S[i][j] - mnew);
                psum += S[i][j];
            }
#pragma unroll
            for (int o = 1; o < 16; o <<= 1)
                psum += __shfl_xor_sync(0xffffffffu, psum, o);
            l_i[i] = l_i[i]*alpha + psum;
            m_i[i] = mnew;
#pragma unroll
            for (int j = 0; j < 4; j++) O[i][j] *= alpha;
            // store P row (natural layout, coalesced float4)
            *reinterpret_cast<float4*>(&Ps[ty*4+i][tx*4]) =
                make_float4(S[i][0], S[i][1], S[i][2], S[i][3]);
        }
        __syncthreads();   // Ps visible; KVs(K) free

        // load V natural
#pragma unroll
        for (int r0 = 0; r0 < 64; r0 += 16) {
            int r = r0 + ty;
            *reinterpret_cast<float4*>(&KVs[r][tx*4]) =
                *reinterpret_cast<const float4*>(&Vp[(size_t)(k0+r)*HD + tx*4]);
        }
        __syncthreads();

        // O += P * V
#pragma unroll
        for (int kk = 0; kk < 64; kk++) {
            float pa[4];
#pragma unroll
            for (int i = 0; i < 4; i++) pa[i] = Ps[ty*4+i][kk];   // broadcast reads
            float4 vb = *reinterpret_cast<const float4*>(&KVs[kk][tx*4]);
            float rb[4] = {vb.x, vb.y, vb.z, vb.w};
#pragma unroll
            for (int i = 0; i < 4; i++)
#pragma unroll
                for (int j = 0; j < 4; j++)
                    O[i][j] = fmaf(pa[i], rb[j], O[i][j]);
        }
    }

    // epilogue: normalize + write [B,N,C] with head-concat layout
    float* Op = g_ao + ((size_t)b*NUM_N + q0)*NUM_C + h*HD;
#pragma unroll
    for (int i = 0; i < 4; i++) {
        float inv = 1.0f / l_i[i];
        *reinterpret_cast<float4*>(&Op[(size_t)(ty*4+i)*NUM_C + tx*4]) =
            make_float4(O[i][0]*inv, O[i][1]*inv, O[i][2]*inv, O[i][3]*inv);
    }
}

// ---------------------------------------------------------------------------
// Kernel 4: output projection.  out[m,n] = sum_k ao[m,k]*w_proj[n,k] + b[n]
// M=4096, N=1024, K=1024.  Same SGEMM structure.
// ---------------------------------------------------------------------------
__global__ __launch_bounds__(256) void proj_gemm(const float* __restrict__ W,
                                                 const float* __restrict__ bias,
                                                 float* __restrict__ out) {
    __shared__ float As[16][128];
    __shared__ float Bs[16][128];
    const int tid = threadIdx.x;
    const int bm = blockIdx.y * 128;
    const int bn = blockIdx.x * 128;
    const int tx = tid & 15, ty = tid >> 4;
    const int lr = tid >> 2;
    const int lc = (tid & 3) * 4;

    float acc[8][8] = {};

    for (int k0 = 0; k0 < NUM_C; k0 += 16) {
#pragma unroll
        for (int i = 0; i < 2; i++) {
            float4 a4 = *reinterpret_cast<const float4*>(&g_ao[(size_t)(bm + lr + i*64)*NUM_C + k0 + lc]);
            As[lc+0][lr+i*64] = a4.x; As[lc+1][lr+i*64] = a4.y;
            As[lc+2][lr+i*64] = a4.z; As[lc+3][lr+i*64] = a4.w;
            float4 b4 = *reinterpret_cast<const float4*>(&W[(size_t)(bn + lr + i*64)*NUM_C + k0 + lc]);
            Bs[lc+0][lr+i*64] = b4.x; Bs[lc+1][lr+i*64] = b4.y;
            Bs[lc+2][lr+i*64] = b4.z; Bs[lc+3][lr+i*64] = b4.w;
        }
        __syncthreads();
#pragma unroll
        for (int k = 0; k < 16; k++) {
            float ra[8], rb[8];
            *reinterpret_cast<float4*>(&ra[0]) = *reinterpret_cast<const float4*>(&As[k][ty*4]);
            *reinterpret_cast<float4*>(&ra[4]) = *reinterpret_cast<const float4*>(&As[k][64+ty*4]);
            *reinterpret_cast<float4*>(&rb[0]) = *reinterpret_cast<const float4*>(&Bs[k][tx*4]);
            *reinterpret_cast<float4*>(&rb[4]) = *reinterpret_cast<const float4*>(&Bs[k][64+tx*4]);
#pragma unroll
            for (int i = 0; i < 8; i++)
#pragma unroll
                for (int j = 0; j < 8; j++)
                    acc[i][j] = fmaf(ra[i], rb[j], acc[i][j]);
        }
        __syncthreads();
    }

#pragma unroll
    for (int ih = 0; ih < 2; ih++) {
#pragma unroll
        for (int i = 0; i < 4; i++) {
            int m = bm + ih*64 + ty*4 + i;
#pragma unroll
            for (int jh = 0; jh < 2; jh++) {
                int n = bn + jh*64 + tx*4;
                float4 bv = *reinterpret_cast<const float4*>(&bias[n]);
                float4 v4 = make_float4(acc[ih*4+i][jh*4+0] + bv.x,
                                        acc[ih*4+i][jh*4+1] + bv.y,
                                        acc[ih*4+i][jh*4+2] + bv.z,
                                        acc[ih*4+i][jh*4+3] + bv.w);
                *reinterpret_cast<float4*>(&out[(size_t)m*NUM_C + n]) = v4;
            }
        }
    }
}

// ---------------------------------------------------------------------------
extern "C" void kernel_launch(void* const* d_in, const int* in_sizes, int n_in,
                              void* d_out, int out_size) {
    const float* x       = (const float*)d_in[0];
    const unsigned char* mask = (const unsigned char*)d_in[1];
    const float* w_qkv   = (const float*)d_in[2];
    const float* w_proj  = (const float*)d_in[3];
    const float* b_proj  = (const float*)d_in[4];
    const float* q_gamma = (const float*)d_in[5];
    const float* q_beta  = (const float*)d_in[6];
    const float* k_gamma = (const float*)d_in[7];
    const float* k_beta  = (const float*)d_in[8];
    float* out = (float*)d_out;

    // resolve device-symbol addresses for LN (same symbols kernels use directly)
    float* dq = nullptr; float* dk = nullptr;
    cudaGetSymbolAddress((void**)&dq, g_q);
    cudaGetSymbolAddress((void**)&dk, g_k);

    // 1) QKV GEMM  (grid: N-tiles x M-tiles)
    qkv_gemm<<<dim3(3*NUM_C/128, MTOT/128), 256>>>(x, w_qkv);

    // 2) LayerNorm on q and k  (B*H*N rows each, 8 rows/block)
    const int rows = NUM_B*NUM_H*NUM_N;
    ln_kernel<<<rows/8, 256>>>(dq, q_gamma, q_beta);
    ln_kernel<<<rows/8, 256>>>(dk, k_gamma, k_beta);

    // 3) flash attention
    attn_kernel<<<dim3(NUM_N/64, NUM_B*NUM_H), 256>>>(mask);

    // 4) output projection + bias
    proj_gemm<<<dim3(NUM_C/128, MTOT/128), 256>>>(w_proj, b_proj, out);
}

// round 7
// speedup vs baseline: 1.1166x; 1.1166x over previous
#include <cuda_runtime.h>
#include <math.h>

#define NUM_B 2
#define NUM_N 2048
#define NUM_C 1024
#define NUM_H 16
#define HD    64
#define MTOT  (NUM_B*NUM_N)      /* 4096 */

// Scratch (allocation-free: __device__ globals)
__device__ float g_q[NUM_B*NUM_H*NUM_N*HD];   // 16 MB
__device__ float g_k[NUM_B*NUM_H*NUM_N*HD];
__device__ float g_v[NUM_B*NUM_H*NUM_N*HD];
__device__ float g_ao[NUM_B*NUM_N*NUM_C];     // attention out, [B,N,C]

// ---------------------------------------------------------------------------
// Kernel 1: QKV GEMM.  out[m,n] = sum_k x[m,k] * w_qkv[n,k]   (NT)
// M=4096, N=3072, K=1024.  BM=BN=128, BK=16, 256 thr, 8x8/thread.
// Double-buffered smem (register-staged prefetch), 1 sync / k-iter.
// Epilogue scatters into g_q/g_k/g_v laid out [B,H,N,d].
// ---------------------------------------------------------------------------
__global__ __launch_bounds__(256) void qkv_gemm(const float* __restrict__ A,
                                                const float* __restrict__ W) {
    __shared__ float As[2][16][128];
    __shared__ float Bs[2][16][128];
    const int tid = threadIdx.x;
    const int bm = blockIdx.y * 128;
    const int bn = blockIdx.x * 128;
    const int tx = tid & 15, ty = tid >> 4;
    const int lr = tid >> 2;          // 0..63
    const int lc = (tid & 3) * 4;     // 0,4,8,12

    float acc[8][8] = {};
    float4 an[2], bnx[2];

#pragma unroll
    for (int i = 0; i < 2; i++) {
        an[i]  = *reinterpret_cast<const float4*>(&A[(size_t)(bm + lr + i*64)*NUM_C + lc]);
        bnx[i] = *reinterpret_cast<const float4*>(&W[(size_t)(bn + lr + i*64)*NUM_C + lc]);
    }

    int buf = 0;
    for (int k0 = 0; k0 < NUM_C; k0 += 16) {
        // commit staged tile to smem
#pragma unroll
        for (int i = 0; i < 2; i++) {
            As[buf][lc+0][lr+i*64] = an[i].x; As[buf][lc+1][lr+i*64] = an[i].y;
            As[buf][lc+2][lr+i*64] = an[i].z; As[buf][lc+3][lr+i*64] = an[i].w;
            Bs[buf][lc+0][lr+i*64] = bnx[i].x; Bs[buf][lc+1][lr+i*64] = bnx[i].y;
            Bs[buf][lc+2][lr+i*64] = bnx[i].z; Bs[buf][lc+3][lr+i*64] = bnx[i].w;
        }
        __syncthreads();
        // prefetch next tile (latency overlapped with compute below)
        if (k0 + 16 < NUM_C) {
#pragma unroll
            for (int i = 0; i < 2; i++) {
                an[i]  = *reinterpret_cast<const float4*>(&A[(size_t)(bm + lr + i*64)*NUM_C + k0 + 16 + lc]);
                bnx[i] = *reinterpret_cast<const float4*>(&W[(size_t)(bn + lr + i*64)*NUM_C + k0 + 16 + lc]);
            }
        }
#pragma unroll
        for (int k = 0; k < 16; k++) {
            float ra[8], rb[8];
            *reinterpret_cast<float4*>(&ra[0]) = *reinterpret_cast<const float4*>(&As[buf][k][ty*4]);
            *reinterpret_cast<float4*>(&ra[4]) = *reinterpret_cast<const float4*>(&As[buf][k][64+ty*4]);
            *reinterpret_cast<float4*>(&rb[0]) = *reinterpret_cast<const float4*>(&Bs[buf][k][tx*4]);
            *reinterpret_cast<float4*>(&rb[4]) = *reinterpret_cast<const float4*>(&Bs[buf][k][64+tx*4]);
#pragma unroll
            for (int i = 0; i < 8; i++)
#pragma unroll
                for (int j = 0; j < 8; j++)
                    acc[i][j] = fmaf(ra[i], rb[j], acc[i][j]);
        }
        buf ^= 1;
    }

    const int which = bn >> 10;
    float* dst = (which == 0) ? g_q : ((which == 1) ? g_k : g_v);
#pragma unroll
    for (int ih = 0; ih < 2; ih++) {
#pragma unroll
        for (int i = 0; i < 4; i++) {
            int m   = bm + ih*64 + ty*4 + i;
            int b   = m >> 11;
            int tok = m & 2047;
#pragma unroll
            for (int jh = 0; jh < 2; jh++) {
                int n  = bn + jh*64 + tx*4;
                int c  = n & 1023;
                int h  = c >> 6;
                int d0 = c & 63;
                float4 v4 = make_float4(acc[ih*4+i][jh*4+0], acc[ih*4+i][jh*4+1],
                                        acc[ih*4+i][jh*4+2], acc[ih*4+i][jh*4+3]);
                *reinterpret_cast<float4*>(
                    &dst[(((size_t)(b*NUM_H + h))*NUM_N + tok)*HD + d0]) = v4;
            }
        }
    }
}

// ---------------------------------------------------------------------------
// Kernel 2: flash attention fp32, fused q/k LayerNorm at tile-load time.
// Block = 128 queries of one (b,h). 256 thr (16x16), 8x8 S-microtile,
// 8x4 O-microtile. XOR-swizzled transposed Q/K tiles (2-way store conflicts,
// conflict-free float4 loads). Dynamic smem = 128KB (1 CTA/SM).
// ---------------------------------------------------------------------------
#define ATTN_SMEM (131072)

__global__ __launch_bounds__(256) void attn_kernel(const unsigned char* __restrict__ mask,
                                                   const float* __restrict__ q_gamma,
                                                   const float* __restrict__ q_beta,
                                                   const float* __restrict__ k_gamma,
                                                   const float* __restrict__ k_beta) {
    extern __shared__ float sm[];
    float* Qs = sm;                 // 64 x 128 transposed+swizzled   (32KB)
    float* KV = sm + 64*128;        // K: 64x128 transp+swz ; V: 128x64 natural (32KB)
    float* Ps = sm + 2*64*128;      // 128 x 128 natural              (64KB)

    const int bh = blockIdx.y;            // b*16 + h
    const int b  = bh >> 4;
    const int h  = bh & 15;
    const int q0 = blockIdx.x * 128;

    const float* Qp = g_q + ((size_t)bh*NUM_N + q0)*HD;
    const float* Kp = g_k + (size_t)bh*NUM_N*HD;
    const float* Vp = g_v + (size_t)bh*NUM_N*HD;
    const unsigned char* mp = mask + (size_t)b*NUM_N*NUM_N + (size_t)q0*NUM_N;

    const int tid = threadIdx.x;
    const int tx = tid & 15, ty = tid >> 4;

    // per-thread gamma/beta for columns tx*4..tx*4+3
    const float4 qg4 = *reinterpret_cast<const float4*>(&q_gamma[tx*4]);
    const float4 qb4 = *reinterpret_cast<const float4*>(&q_beta [tx*4]);
    const float4 kg4 = *reinterpret_cast<const float4*>(&k_gamma[tx*4]);
    const float4 kb4 = *reinterpret_cast<const float4*>(&k_beta [tx*4]);

    // ---- load Q tile: LayerNorm + scale, store transposed+swizzled ----
    // element (d, q) lives at Qs[d*128 + (((q>>2) ^ (d>>2 & 7))<<2) + (q&3)]
#pragma unroll
    for (int j = 0; j < 8; j++) {
        int r = j*16 + ty;                       // local q row
        float4 v = *reinterpret_cast<const float4*>(&Qp[(size_t)r*HD + tx*4]);
        float s  = v.x + v.y + v.z + v.w;
        float ss = v.x*v.x + v.y*v.y + v.z*v.z + v.w*v.w;
#pragma unroll
        for (int o = 8; o > 0; o >>= 1) {
            s  += __shfl_xor_sync(0xffffffffu, s,  o);
            ss += __shfl_xor_sync(0xffffffffu, ss, o);
        }
        float mu  = s * (1.0f/64.0f);
        float var = ss * (1.0f/64.0f) - mu*mu;
        float inv = rsqrtf(var + 1e-5f) * 0.125f;   // fold 1/sqrt(64) attn scale
        float o0 = (v.x - mu)*inv*qg4.x + qb4.x*0.125f;
        float o1 = (v.y - mu)*inv*qg4.y + qb4.y*0.125f;
        float o2 = (v.z - mu)*inv*qg4.z + qb4.z*0.125f;
        float o3 = (v.w - mu)*inv*qg4.w + qb4.w*0.125f;
        int base = ((((r>>2) ^ (tx & 7)) << 2) + (r & 3));  // d>>2 == tx for d=tx*4+cc
        Qs[(tx*4+0)*128 + base] = o0;
        Qs[(tx*4+1)*128 + base] = o1;
        Qs[(tx*4+2)*128 + base] = o2;
        Qs[(tx*4+3)*128 + base] = o3;
    }

    float m_i[8], l_i[8], O[8][4];
#pragma unroll
    for (int i = 0; i < 8; i++) {
        m_i[i] = -3.402823466e38f; l_i[i] = 0.0f;
#pragma unroll
        for (int j = 0; j < 4; j++) O[i][j] = 0.0f;
    }

    for (int kt = 0; kt < NUM_N/128; kt++) {
        const int k0 = kt * 128;
        __syncthreads();   // prev O-gemm done reading KV/Ps (and Qs stores on iter 0)

        // ---- load K tile: LayerNorm, store transposed+swizzled ----
#pragma unroll
        for (int j = 0; j < 8; j++) {
            int r = j*16 + ty;                   // local k row
            float4 v = *reinterpret_cast<const float4*>(&Kp[(size_t)(k0+r)*HD + tx*4]);
            float s  = v.x + v.y + v.z + v.w;
            float ss = v.x*v.x + v.y*v.y + v.z*v.z + v.w*v.w;
#pragma unroll
            for (int o = 8; o > 0; o >>= 1) {
                s  += __shfl_xor_sync(0xffffffffu, s,  o);
                ss += __shfl_xor_sync(0xffffffffu, ss, o);
            }
            float mu  = s * (1.0f/64.0f);
            float var = ss * (1.0f/64.0f) - mu*mu;
            float inv = rsqrtf(var + 1e-5f);
            float o0 = (v.x - mu)*inv*kg4.x + kb4.x;
            float o1 = (v.y - mu)*inv*kg4.y + kb4.y;
            float o2 = (v.z - mu)*inv*kg4.z + kb4.z;
            float o3 = (v.w - mu)*inv*kg4.w + kb4.w;
            int base = ((((r>>2) ^ (tx & 7)) << 2) + (r & 3));
            KV[(tx*4+0)*128 + base] = o0;
            KV[(tx*4+1)*128 + base] = o1;
            KV[(tx*4+2)*128 + base] = o2;
            KV[(tx*4+3)*128 + base] = o3;
        }
        __syncthreads();

        // ---- S = Q * K^T (128x128x64), 8x8 per thread ----
        float S[8][8] = {};
#pragma unroll
        for (int dd = 0; dd < 64; dd++) {
            const int sw = (dd >> 2) & 7;
            float ra[8], rb[8];
            const float4* Q4 = reinterpret_cast<const float4*>(&Qs[dd*128]);
            const float4* K4 = reinterpret_cast<const float4*>(&KV[dd*128]);
            *reinterpret_cast<float4*>(&ra[0]) = Q4[(ty*2+0) ^ sw];
            *reinterpret_cast<float4*>(&ra[4]) = Q4[(ty*2+1) ^ sw];
            *reinterpret_cast<float4*>(&rb[0]) = K4[(tx*2+0) ^ sw];
            *reinterpret_cast<float4*>(&rb[4]) = K4[(tx*2+1) ^ sw];
#pragma unroll
            for (int i = 0; i < 8; i++)
#pragma unroll
                for (int j = 0; j < 8; j++)
                    S[i][j] = fmaf(ra[i], rb[j], S[i][j]);
        }

        // ---- mask + online softmax ----
#pragma unroll
        for (int i = 0; i < 8; i++) {
            const unsigned char* mrow = &mp[(size_t)(ty*8+i)*NUM_N + k0 + tx*8];
            uchar4 m0 = *reinterpret_cast<const uchar4*>(mrow);
            uchar4 m1 = *reinterpret_cast<const uchar4*>(mrow + 4);
            if (m0.x) S[i][0] = -3.402823466e38f;
            if (m0.y) S[i][1] = -3.402823466e38f;
            if (m0.z) S[i][2] = -3.402823466e38f;
            if (m0.w) S[i][3] = -3.402823466e38f;
            if (m1.x) S[i][4] = -3.402823466e38f;
            if (m1.y) S[i][5] = -3.402823466e38f;
            if (m1.z) S[i][6] = -3.402823466e38f;
            if (m1.w) S[i][7] = -3.402823466e38f;

            float rmax = S[i][0];
#pragma unroll
            for (int j = 1; j < 8; j++) rmax = fmaxf(rmax, S[i][j]);
#pragma unroll
            for (int o = 1; o < 16; o <<= 1)
                rmax = fmaxf(rmax, __shfl_xor_sync(0xffffffffu, rmax, o));
            float mnew  = fmaxf(m_i[i], rmax);
            float alpha = __expf(m_i[i] - mnew);
            float psum = 0.0f;
#pragma unroll
            for (int j = 0; j < 8; j++) {
                S[i][j] = __expf(S[i][j] - mnew);
                psum += S[i][j];
            }
#pragma unroll
            for (int o = 1; o < 16; o <<= 1)
                psum += __shfl_xor_sync(0xffffffffu, psum, o);
            l_i[i] = l_i[i]*alpha + psum;
            m_i[i] = mnew;
#pragma unroll
            for (int j = 0; j < 4; j++) O[i][j] *= alpha;
            *reinterpret_cast<float4*>(&Ps[(ty*8+i)*128 + tx*8])     =
                make_float4(S[i][0], S[i][1], S[i][2], S[i][3]);
            *reinterpret_cast<float4*>(&Ps[(ty*8+i)*128 + tx*8 + 4]) =
                make_float4(S[i][4], S[i][5], S[i][6], S[i][7]);
        }
        __syncthreads();   // Ps visible; KV(K) reads done

        // ---- load V tile (natural [k][d]) ----
#pragma unroll
        for (int j = 0; j < 8; j++) {
            int r = j*16 + ty;
            *reinterpret_cast<float4*>(&KV[r*64 + tx*4]) =
                *reinterpret_cast<const float4*>(&Vp[(size_t)(k0+r)*HD + tx*4]);
        }
        __syncthreads();

        // ---- O += P * V  (128x64x128), float4-chunked over k ----
        const float4* P4 = reinterpret_cast<const float4*>(Ps);
        const float4* V4 = reinterpret_cast<const float4*>(KV);
#pragma unroll 4
        for (int kk4 = 0; kk4 < 32; kk4++) {
            float4 vb[4];
#pragma unroll
            for (int t = 0; t < 4; t++) vb[t] = V4[(kk4*4+t)*16 + tx];
#pragma unroll
            for (int i = 0; i < 8; i++) {
                float4 p = P4[(ty*8+i)*32 + kk4];
                O[i][0] = fmaf(p.x, vb[0].x, O[i][0]);
                O[i][1] = fmaf(p.x, vb[0].y, O[i][1]);
                O[i][2] = fmaf(p.x, vb[0].z, O[i][2]);
                O[i][3] = fmaf(p.x, vb[0].w, O[i][3]);
                O[i][0] = fmaf(p.y, vb[1].x, O[i][0]);
                O[i][1] = fmaf(p.y, vb[1].y, O[i][1]);
                O[i][2] = fmaf(p.y, vb[1].z, O[i][2]);
                O[i][3] = fmaf(p.y, vb[1].w, O[i][3]);
                O[i][0] = fmaf(p.z, vb[2].x, O[i][0]);
                O[i][1] = fmaf(p.z, vb[2].y, O[i][1]);
                O[i][2] = fmaf(p.z, vb[2].z, O[i][2]);
                O[i][3] = fmaf(p.z, vb[2].w, O[i][3]);
                O[i][0] = fmaf(p.w, vb[3].x, O[i][0]);
                O[i][1] = fmaf(p.w, vb[3].y, O[i][1]);
                O[i][2] = fmaf(p.w, vb[3].z, O[i][2]);
                O[i][3] = fmaf(p.w, vb[3].w, O[i][3]);
            }
        }
    }

    // epilogue: normalize + write [B,N,C] head-concat layout
    float* Op = g_ao + ((size_t)b*NUM_N + q0)*NUM_C + h*HD;
#pragma unroll
    for (int i = 0; i < 8; i++) {
        float inv = 1.0f / l_i[i];
        *reinterpret_cast<float4*>(&Op[(size_t)(ty*8+i)*NUM_C + tx*4]) =
            make_float4(O[i][0]*inv, O[i][1]*inv, O[i][2]*inv, O[i][3]*inv);
    }
}

// ---------------------------------------------------------------------------
// Kernel 3: output projection.  out[m,n] = sum_k ao[m,k]*w_proj[n,k] + b[n]
// M=4096, N=1024, K=1024.  Double-buffered like qkv_gemm.
// ---------------------------------------------------------------------------
__global__ __launch_bounds__(256) void proj_gemm(const float* __restrict__ W,
                                                 const float* __restrict__ bias,
                                                 float* __restrict__ out) {
    __shared__ float As[2][16][128];
    __shared__ float Bs[2][16][128];
    const int tid = threadIdx.x;
    const int bm = blockIdx.y * 128;
    const int bn = blockIdx.x * 128;
    const int tx = tid & 15, ty = tid >> 4;
    const int lr = tid >> 2;
    const int lc = (tid & 3) * 4;

    float acc[8][8] = {};
    float4 an[2], bnx[2];

#pragma unroll
    for (int i = 0; i < 2; i++) {
        an[i]  = *reinterpret_cast<const float4*>(&g_ao[(size_t)(bm + lr + i*64)*NUM_C + lc]);
        bnx[i] = *reinterpret_cast<const float4*>(&W[(size_t)(bn + lr + i*64)*NUM_C + lc]);
    }

    int buf = 0;
    for (int k0 = 0; k0 < NUM_C; k0 += 16) {
#pragma unroll
        for (int i = 0; i < 2; i++) {
            As[buf][lc+0][lr+i*64] = an[i].x; As[buf][lc+1][lr+i*64] = an[i].y;
            As[buf][lc+2][lr+i*64] = an[i].z; As[buf][lc+3][lr+i*64] = an[i].w;
            Bs[buf][lc+0][lr+i*64] = bnx[i].x; Bs[buf][lc+1][lr+i*64] = bnx[i].y;
            Bs[buf][lc+2][lr+i*64] = bnx[i].z; Bs[buf][lc+3][lr+i*64] = bnx[i].w;
        }
        __syncthreads();
        if (k0 + 16 < NUM_C) {
#pragma unroll
            for (int i = 0; i < 2; i++) {
                an[i]  = *reinterpret_cast<const float4*>(&g_ao[(size_t)(bm + lr + i*64)*NUM_C + k0 + 16 + lc]);
                bnx[i] = *reinterpret_cast<const float4*>(&W[(size_t)(bn + lr + i*64)*NUM_C + k0 + 16 + lc]);
            }
        }
#pragma unroll
        for (int k = 0; k < 16; k++) {
            float ra[8], rb[8];
            *reinterpret_cast<float4*>(&ra[0]) = *reinterpret_cast<const float4*>(&As[buf][k][ty*4]);
            *reinterpret_cast<float4*>(&ra[4]) = *reinterpret_cast<const float4*>(&As[buf][k][64+ty*4]);
            *reinterpret_cast<float4*>(&rb[0]) = *reinterpret_cast<const float4*>(&Bs[buf][k][tx*4]);
            *reinterpret_cast<float4*>(&rb[4]) = *reinterpret_cast<const float4*>(&Bs[buf][k][64+tx*4]);
#pragma unroll
            for (int i = 0; i < 8; i++)
#pragma unroll
                for (int j = 0; j < 8; j++)
                    acc[i][j] = fmaf(ra[i], rb[j], acc[i][j]);
        }
        buf ^= 1;
    }

#pragma unroll
    for (int ih = 0; ih < 2; ih++) {
#pragma unroll
        for (int i = 0; i < 4; i++) {
            int m = bm + ih*64 + ty*4 + i;
#pragma unroll
            for (int jh = 0; jh < 2; jh++) {
                int n = bn + jh*64 + tx*4;
                float4 bv = *reinterpret_cast<const float4*>(&bias[n]);
                float4 v4 = make_float4(acc[ih*4+i][jh*4+0] + bv.x,
                                        acc[ih*4+i][jh*4+1] + bv.y,
                                        acc[ih*4+i][jh*4+2] + bv.z,
                                        acc[ih*4+i][jh*4+3] + bv.w);
                *reinterpret_cast<float4*>(&out[(size_t)m*NUM_C + n]) = v4;
            }
        }
    }
}

// ---------------------------------------------------------------------------
extern "C" void kernel_launch(void* const* d_in, const int* in_sizes, int n_in,
                              void* d_out, int out_size) {
    const float* x       = (const float*)d_in[0];
    const unsigned char* mask = (const unsigned char*)d_in[1];
    const float* w_qkv   = (const float*)d_in[2];
    const float* w_proj  = (const float*)d_in[3];
    const float* b_proj  = (const float*)d_in[4];
    const float* q_gamma = (const float*)d_in[5];
    const float* q_beta  = (const float*)d_in[6];
    const float* k_gamma = (const float*)d_in[7];
    const float* k_beta  = (const float*)d_in[8];
    float* out = (float*)d_out;

    cudaFuncSetAttribute(attn_kernel, cudaFuncAttributeMaxDynamicSharedMemorySize, ATTN_SMEM);

    // 1) QKV GEMM
    qkv_gemm<<<dim3(3*NUM_C/128, MTOT/128), 256>>>(x, w_qkv);

    // 2) flash attention with fused q/k LayerNorm
    attn_kernel<<<dim3(NUM_N/128, NUM_B*NUM_H), 256, ATTN_SMEM>>>(
        mask, q_gamma, q_beta, k_gamma, k_beta);

    // 3) output projection + bias
    proj_gemm<<<dim3(NUM_C/128, MTOT/128), 256>>>(w_proj, b_proj, out);
}

// round 13
// speedup vs baseline: 1.3995x; 1.2533x over previous
#include <cuda_runtime.h>
#include <cuda_bf16.h>
#include <math.h>
#include <cstdint>

#define NUM_B 2
#define NUM_N 2048
#define NUM_C 1024
#define NUM_H 16
#define HD    64
#define MTOT  (NUM_B*NUM_N)      /* 4096 */

// ---------------------------------------------------------------------------
// Scratch (allocation-free: __device__ globals)
// ---------------------------------------------------------------------------
__device__ float g_q[NUM_B*NUM_H*NUM_N*HD];   // 16 MB
__device__ float g_k[NUM_B*NUM_H*NUM_N*HD];
__device__ float g_v[NUM_B*NUM_H*NUM_N*HD];
__device__ float g_ao[NUM_B*NUM_N*NUM_C];     // attention out, [B,N,C]

// split-bf16 copies (hi/lo) for tensor-core GEMMs
__device__ __nv_bfloat16 g_xh [MTOT*NUM_C];
__device__ __nv_bfloat16 g_xl [MTOT*NUM_C];
__device__ __nv_bfloat16 g_wqh[3*NUM_C*NUM_C];
__device__ __nv_bfloat16 g_wql[3*NUM_C*NUM_C];
__device__ __nv_bfloat16 g_aoh[MTOT*NUM_C];
__device__ __nv_bfloat16 g_aol[MTOT*NUM_C];
__device__ __nv_bfloat16 g_wph[NUM_C*NUM_C];
__device__ __nv_bfloat16 g_wpl[NUM_C*NUM_C];

// ---------------------------------------------------------------------------
// mma.sync helper (sm_80+ HMMA; compiles under compute_103)
// D(f32 m16n8) += A(bf16 m16k16, row) * B(bf16 k16n8, col)
// ---------------------------------------------------------------------------
__device__ __forceinline__ void mma16816(float* d, const uint32_t* a, const uint32_t* b) {
    asm volatile(
        "mma.sync.aligned.m16n8k16.row.col.f32.bf16.bf16.f32 "
        "{%0,%1,%2,%3}, {%4,%5,%6,%7}, {%8,%9}, {%0,%1,%2,%3};"
        : "+f"(d[0]), "+f"(d[1]), "+f"(d[2]), "+f"(d[3])
        : "r"(a[0]), "r"(a[1]), "r"(a[2]), "r"(a[3]), "r"(b[0]), "r"(b[1]));
}

__device__ __forceinline__ uint32_t lds_u32(const __nv_bfloat16* p) {
    return *reinterpret_cast<const uint32_t*>(p);
}

// ---------------------------------------------------------------------------
// Kernel 0: fp32 -> (bf16 hi, bf16 lo) split conversion, 4 elems/thread.
// ---------------------------------------------------------------------------
struct __align__(8) bf4 { __nv_bfloat16 a, b, c, d; };

__global__ __launch_bounds__(256) void split_conv(const float* __restrict__ s,
                                                  __nv_bfloat16* __restrict__ hi,
                                                  __nv_bfloat16* __restrict__ lo,
                                                  int n4) {
    int i = blockIdx.x * blockDim.x + threadIdx.x;
    if (i >= n4) return;
    float4 v = reinterpret_cast<const float4*>(s)[i];
    __nv_bfloat16 h0 = __float2bfloat16(v.x);
    __nv_bfloat16 h1 = __float2bfloat16(v.y);
    __nv_bfloat16 h2 = __float2bfloat16(v.z);
    __nv_bfloat16 h3 = __float2bfloat16(v.w);
    __nv_bfloat16 l0 = __float2bfloat16(v.x - __bfloat162float(h0));
    __nv_bfloat16 l1 = __float2bfloat16(v.y - __bfloat162float(h1));
    __nv_bfloat16 l2 = __float2bfloat16(v.z - __bfloat162float(h2));
    __nv_bfloat16 l3 = __float2bfloat16(v.w - __bfloat162float(h3));
    bf4 hh = {h0, h1, h2, h3};
    bf4 ll = {l0, l1, l2, l3};
    reinterpret_cast<bf4*>(hi)[i] = hh;
    reinterpret_cast<bf4*>(lo)[i] = ll;
}

// ---------------------------------------------------------------------------
// Kernel 1/3: mma.sync bf16-split GEMM.  D[m,n] = sum_k A[m,k]*B[n,k]  (NT)
// Block 128x128, BK=32, 256 thr = 8 warps (4m x 2n), warp tile 32m x 64n.
// 3 split terms: AhBh + AhBl + AlBh.  Double-buffered smem, reg prefetch.
// Smem rows padded to LDA=40 bf16 (80B) -> conflict-free fragment LDS.
// EPI=0: scatter into g_q/g_k/g_v [B,H,N,d].  EPI=1: out + bias.
// ---------------------------------------------------------------------------
#define LDA 40
#define STAGE_ELE (4*128*LDA)            /* Ah,Al,Bh,Bl per stage  */
#define GEMM_SMEM (2*STAGE_ELE*2)        /* bytes: 81920 */

template<int EPI>
__global__ __launch_bounds__(256) void mma_gemm(const __nv_bfloat16* __restrict__ Ah,
                                                const __nv_bfloat16* __restrict__ Al,
                                                const __nv_bfloat16* __restrict__ Bh,
                                                const __nv_bfloat16* __restrict__ Bl,
                                                const float* __restrict__ bias,
                                                float* __restrict__ outp) {
    extern __shared__ __nv_bfloat16 smem[];
    const int tid  = threadIdx.x;
    const int wid  = tid >> 5, lane = tid & 31;
    const int wm   = wid >> 1;            // 0..3  (m-warp)
    const int wn   = wid & 1;             // 0..1  (n-warp)
    const int g    = lane >> 2;           // group 0..7
    const int tg   = lane & 3;            // 0..3
    const int bm   = blockIdx.y * 128;
    const int bn   = blockIdx.x * 128;

    // loader mapping: 2 threads per row, 16 bf16 (2 x uint4) each
    const int lrow = tid >> 1;            // 0..127
    const int lhalf = (tid & 1) * 16;     // 0 or 16 (bf16 elems)
    const __nv_bfloat16* gah = Ah + (size_t)(bm + lrow) * NUM_C + lhalf;
    const __nv_bfloat16* gal = Al + (size_t)(bm + lrow) * NUM_C + lhalf;
    const __nv_bfloat16* gbh = Bh + (size_t)(bn + lrow) * NUM_C + lhalf;
    const __nv_bfloat16* gbl = Bl + (size_t)(bn + lrow) * NUM_C + lhalf;
    const int soff = lrow * LDA + lhalf;

    float acc[2][8][4];
#pragma unroll
    for (int i = 0; i < 2; i++)
#pragma unroll
        for (int j = 0; j < 8; j++)
#pragma unroll
            for (int t = 0; t < 4; t++) acc[i][j][t] = 0.0f;

    uint4 pr[8];   // prefetch regs: {ah0,ah1, al0,al1, bh0,bh1, bl0,bl1}
    pr[0] = *reinterpret_cast<const uint4*>(gah);
    pr[1] = *reinterpret_cast<const uint4*>(gah + 8);
    pr[2] = *reinterpret_cast<const uint4*>(gal);
    pr[3] = *reinterpret_cast<const uint4*>(gal + 8);
    pr[4] = *reinterpret_cast<const uint4*>(gbh);
    pr[5] = *reinterpret_cast<const uint4*>(gbh + 8);
    pr[6] = *reinterpret_cast<const uint4*>(gbl);
    pr[7] = *reinterpret_cast<const uint4*>(gbl + 8);

    for (int c = 0; c < NUM_C/32; c++) {
        const int s = c & 1;
        __nv_bfloat16* st = smem + s * STAGE_ELE;
        __nv_bfloat16* sAh = st;
        __nv_bfloat16* sAl = st + 128*LDA;
        __nv_bfloat16* sBh = st + 2*128*LDA;
        __nv_bfloat16* sBl = st + 3*128*LDA;

        // commit staged tile
        *reinterpret_cast<uint4*>(sAh + soff)     = pr[0];
        *reinterpret_cast<uint4*>(sAh + soff + 8) = pr[1];
        *reinterpret_cast<uint4*>(sAl + soff)     = pr[2];
        *reinterpret_cast<uint4*>(sAl + soff + 8) = pr[3];
        *reinterpret_cast<uint4*>(sBh + soff)     = pr[4];
        *reinterpret_cast<uint4*>(sBh + soff + 8) = pr[5];
        *reinterpret_cast<uint4*>(sBl + soff)     = pr[6];
        *reinterpret_cast<uint4*>(sBl + soff + 8) = pr[7];
        __syncthreads();

        // prefetch next chunk
        if (c + 1 < NUM_C/32) {
            const int go = (c + 1) * 32;
            pr[0] = *reinterpret_cast<const uint4*>(gah + go);
            pr[1] = *reinterpret_cast<const uint4*>(gah + go + 8);
            pr[2] = *reinterpret_cast<const uint4*>(gal + go);
            pr[3] = *reinterpret_cast<const uint4*>(gal + go + 8);
            pr[4] = *reinterpret_cast<const uint4*>(gbh + go);
            pr[5] = *reinterpret_cast<const uint4*>(gbh + go + 8);
            pr[6] = *reinterpret_cast<const uint4*>(gbl + go);
            pr[7] = *reinterpret_cast<const uint4*>(gbl + go + 8);
        }

        // compute: 2 k16 steps
#pragma unroll
        for (int ks = 0; ks < 2; ks++) {
            const int kb = ks * 16;
            uint32_t fah[2][4], fal[2][4];
#pragma unroll
            for (int mf = 0; mf < 2; mf++) {
                const int am = wm*32 + mf*16;
                fah[mf][0] = lds_u32(&sAh[(am + g    )*LDA + kb + tg*2]);
                fah[mf][1] = lds_u32(&sAh[(am + g + 8)*LDA + kb + tg*2]);
                fah[mf][2] = lds_u32(&sAh[(am + g    )*LDA + kb + tg*2 + 8]);
                fah[mf][3] = lds_u32(&sAh[(am + g + 8)*LDA + kb + tg*2 + 8]);
                fal[mf][0] = lds_u32(&sAl[(am + g    )*LDA + kb + tg*2]);
                fal[mf][1] = lds_u32(&sAl[(am + g + 8)*LDA + kb + tg*2]);
                fal[mf][2] = lds_u32(&sAl[(am + g    )*LDA + kb + tg*2 + 8]);
                fal[mf][3] = lds_u32(&sAl[(am + g + 8)*LDA + kb + tg*2 + 8]);
            }
#pragma unroll
            for (int nf = 0; nf < 8; nf++) {
                const int bnr = wn*64 + nf*8 + g;
                uint32_t fbh[2], fbl[2];
                fbh[0] = lds_u32(&sBh[bnr*LDA + kb + tg*2]);
                fbh[1] = lds_u32(&sBh[bnr*LDA + kb + tg*2 + 8]);
                fbl[0] = lds_u32(&sBl[bnr*LDA + kb + tg*2]);
                fbl[1] = lds_u32(&sBl[bnr*LDA + kb + tg*2 + 8]);
#pragma unroll
                for (int mf = 0; mf < 2; mf++) {
                    mma16816(acc[mf][nf], fah[mf], fbh);   // hi*hi
                    mma16816(acc[mf][nf], fah[mf], fbl);   // hi*lo
                    mma16816(acc[mf][nf], fal[mf], fbh);   // lo*hi
                }
            }
        }
        __syncthreads();
    }

    // epilogue.  D row = bm + wm*32 + mf*16 + g (+8), col = bn + wn*64 + nf*8 + tg*2
    if (EPI == 0) {
        const int n0 = bn + wn*64;
        const int which = n0 >> 10;
        const int h = (n0 & 1023) >> 6;
        float* base = (which == 0) ? g_q : ((which == 1) ? g_k : g_v);
#pragma unroll
        for (int mf = 0; mf < 2; mf++) {
#pragma unroll
            for (int half = 0; half < 2; half++) {
                const int mrow = bm + wm*32 + mf*16 + g + half*8;
                float* dst = base + (((size_t)((mrow >> 11) * NUM_H + h)) * NUM_N
                                     + (mrow & 2047)) * HD + (n0 & 63);
#pragma unroll
                for (int nf = 0; nf < 8; nf++) {
                    *reinterpret_cast<float2*>(dst + nf*8 + tg*2) =
                        make_float2(acc[mf][nf][half*2], acc[mf][nf][half*2+1]);
                }
            }
        }
    } else {
#pragma unroll
        for (int mf = 0; mf < 2; mf++) {
#pragma unroll
            for (int half = 0; half < 2; half++) {
                const int mrow = bm + wm*32 + mf*16 + g + half*8;
                float* dst = outp + (size_t)mrow * NUM_C + bn + wn*64;
#pragma unroll
                for (int nf = 0; nf < 8; nf++) {
                    const int col = bn + wn*64 + nf*8 + tg*2;
                    *reinterpret_cast<float2*>(dst + nf*8 + tg*2) =
                        make_float2(acc[mf][nf][half*2] + bias[col],
                                    acc[mf][nf][half*2+1] + bias[col+1]);
                }
            }
        }
    }
}

// ---------------------------------------------------------------------------
// Kernel 2: flash attention fp32, fused q/k LayerNorm at tile-load time.
// (unchanged from R7 — 128q x 128k tiles, 8x8 microtile, swizzled transposes)
// ---------------------------------------------------------------------------
#define ATTN_SMEM (131072)

__global__ __launch_bounds__(256) void attn_kernel(const unsigned char* __restrict__ mask,
                                                   const float* __restrict__ q_gamma,
                                                   const float* __restrict__ q_beta,
                                                   const float* __restrict__ k_gamma,
                                                   const float* __restrict__ k_beta) {
    extern __shared__ float sm[];
    float* Qs = sm;                 // 64 x 128 transposed+swizzled   (32KB)
    float* KV = sm + 64*128;        // K: 64x128 transp+swz ; V: 128x64 natural (32KB)
    float* Ps = sm + 2*64*128;      // 128 x 128 natural              (64KB)

    const int bh = blockIdx.y;
    const int b  = bh >> 4;
    const int h  = bh & 15;
    const int q0 = blockIdx.x * 128;

    const float* Qp = g_q + ((size_t)bh*NUM_N + q0)*HD;
    const float* Kp = g_k + (size_t)bh*NUM_N*HD;
    const float* Vp = g_v + (size_t)bh*NUM_N*HD;
    const unsigned char* mp = mask + (size_t)b*NUM_N*NUM_N + (size_t)q0*NUM_N;

    const int tid = threadIdx.x;
    const int tx = tid & 15, ty = tid >> 4;

    const float4 qg4 = *reinterpret_cast<const float4*>(&q_gamma[tx*4]);
    const float4 qb4 = *reinterpret_cast<const float4*>(&q_beta [tx*4]);
    const float4 kg4 = *reinterpret_cast<const float4*>(&k_gamma[tx*4]);
    const float4 kb4 = *reinterpret_cast<const float4*>(&k_beta [tx*4]);

#pragma unroll
    for (int j = 0; j < 8; j++) {
        int r = j*16 + ty;
        float4 v = *reinterpret_cast<const float4*>(&Qp[(size_t)r*HD + tx*4]);
        float s  = v.x + v.y + v.z + v.w;
        float ss = v.x*v.x + v.y*v.y + v.z*v.z + v.w*v.w;
#pragma unroll
        for (int o = 8; o > 0; o >>= 1) {
            s  += __shfl_xor_sync(0xffffffffu, s,  o);
            ss += __shfl_xor_sync(0xffffffffu, ss, o);
        }
        float mu  = s * (1.0f/64.0f);
        float var = ss * (1.0f/64.0f) - mu*mu;
        float inv = rsqrtf(var + 1e-5f) * 0.125f;
        float o0 = (v.x - mu)*inv*qg4.x + qb4.x*0.125f;
        float o1 = (v.y - mu)*inv*qg4.y + qb4.y*0.125f;
        float o2 = (v.z - mu)*inv*qg4.z + qb4.z*0.125f;
        float o3 = (v.w - mu)*inv*qg4.w + qb4.w*0.125f;
        int base = ((((r>>2) ^ (tx & 7)) << 2) + (r & 3));
        Qs[(tx*4+0)*128 + base] = o0;
        Qs[(tx*4+1)*128 + base] = o1;
        Qs[(tx*4+2)*128 + base] = o2;
        Qs[(tx*4+3)*128 + base] = o3;
    }

    float m_i[8], l_i[8], O[8][4];
#pragma unroll
    for (int i = 0; i < 8; i++) {
        m_i[i] = -3.402823466e38f; l_i[i] = 0.0f;
#pragma unroll
        for (int j = 0; j < 4; j++) O[i][j] = 0.0f;
    }

    for (int kt = 0; kt < NUM_N/128; kt++) {
        const int k0 = kt * 128;
        __syncthreads();

#pragma unroll
        for (int j = 0; j < 8; j++) {
            int r = j*16 + ty;
            float4 v = *reinterpret_cast<const float4*>(&Kp[(size_t)(k0+r)*HD + tx*4]);
            float s  = v.x + v.y + v.z + v.w;
            float ss = v.x*v.x + v.y*v.y + v.z*v.z + v.w*v.w;
#pragma unroll
            for (int o = 8; o > 0; o >>= 1) {
                s  += __shfl_xor_sync(0xffffffffu, s,  o);
                ss += __shfl_xor_sync(0xffffffffu, ss, o);
            }
            float mu  = s * (1.0f/64.0f);
            float var = ss * (1.0f/64.0f) - mu*mu;
            float inv = rsqrtf(var + 1e-5f);
            float o0 = (v.x - mu)*inv*kg4.x + kb4.x;
            float o1 = (v.y - mu)*inv*kg4.y + kb4.y;
            float o2 = (v.z - mu)*inv*kg4.z + kb4.z;
            float o3 = (v.w - mu)*inv*kg4.w + kb4.w;
            int base = ((((r>>2) ^ (tx & 7)) << 2) + (r & 3));
            KV[(tx*4+0)*128 + base] = o0;
            KV[(tx*4+1)*128 + base] = o1;
            KV[(tx*4+2)*128 + base] = o2;
            KV[(tx*4+3)*128 + base] = o3;
        }
        __syncthreads();

        float S[8][8] = {};
#pragma unroll
        for (int dd = 0; dd < 64; dd++) {
            const int sw = (dd >> 2) & 7;
            float ra[8], rb[8];
            const float4* Q4 = reinterpret_cast<const float4*>(&Qs[dd*128]);
            const float4* K4 = reinterpret_cast<const float4*>(&KV[dd*128]);
            *reinterpret_cast<float4*>(&ra[0]) = Q4[(ty*2+0) ^ sw];
            *reinterpret_cast<float4*>(&ra[4]) = Q4[(ty*2+1) ^ sw];
            *reinterpret_cast<float4*>(&rb[0]) = K4[(tx*2+0) ^ sw];
            *reinterpret_cast<float4*>(&rb[4]) = K4[(tx*2+1) ^ sw];
#pragma unroll
            for (int i = 0; i < 8; i++)
#pragma unroll
                for (int j = 0; j < 8; j++)
                    S[i][j] = fmaf(ra[i], rb[j], S[i][j]);
        }

#pragma unroll
        for (int i = 0; i < 8; i++) {
            const unsigned char* mrow = &mp[(size_t)(ty*8+i)*NUM_N + k0 + tx*8];
            uchar4 m0 = *reinterpret_cast<const uchar4*>(mrow);
            uchar4 m1 = *reinterpret_cast<const uchar4*>(mrow + 4);
            if (m0.x) S[i][0] = -3.402823466e38f;
            if (m0.y) S[i][1] = -3.402823466e38f;
            if (m0.z) S[i][2] = -3.402823466e38f;
            if (m0.w) S[i][3] = -3.402823466e38f;
            if (m1.x) S[i][4] = -3.402823466e38f;
            if (m1.y) S[i][5] = -3.402823466e38f;
            if (m1.z) S[i][6] = -3.402823466e38f;
            if (m1.w) S[i][7] = -3.402823466e38f;

            float rmax = S[i][0];
#pragma unroll
            for (int j = 1; j < 8; j++) rmax = fmaxf(rmax, S[i][j]);
#pragma unroll
            for (int o = 1; o < 16; o <<= 1)
                rmax = fmaxf(rmax, __shfl_xor_sync(0xffffffffu, rmax, o));
            float mnew  = fmaxf(m_i[i], rmax);
            float alpha = __expf(m_i[i] - mnew);
            float psum = 0.0f;
#pragma unroll
            for (int j = 0; j < 8; j++) {
                S[i][j] = __expf(S[i][j] - mnew);
                psum += S[i][j];
            }
#pragma unroll
            for (int o = 1; o < 16; o <<= 1)
                psum += __shfl_xor_sync(0xffffffffu, psum, o);
            l_i[i] = l_i[i]*alpha + psum;
            m_i[i] = mnew;
#pragma unroll
            for (int j = 0; j < 4; j++) O[i][j] *= alpha;
            *reinterpret_cast<float4*>(&Ps[(ty*8+i)*128 + tx*8])     =
                make_float4(S[i][0], S[i][1], S[i][2], S[i][3]);
            *reinterpret_cast<float4*>(&Ps[(ty*8+i)*128 + tx*8 + 4]) =
                make_float4(S[i][4], S[i][5], S[i][6], S[i][7]);
        }
        __syncthreads();

#pragma unroll
        for (int j = 0; j < 8; j++) {
            int r = j*16 + ty;
            *reinterpret_cast<float4*>(&KV[r*64 + tx*4]) =
                *reinterpret_cast<const float4*>(&Vp[(size_t)(k0+r)*HD + tx*4]);
        }
        __syncthreads();

        const float4* P4 = reinterpret_cast<const float4*>(Ps);
        const float4* V4 = reinterpret_cast<const float4*>(KV);
#pragma unroll 4
        for (int kk4 = 0; kk4 < 32; kk4++) {
            float4 vb[4];
#pragma unroll
            for (int t = 0; t < 4; t++) vb[t] = V4[(kk4*4+t)*16 + tx];
#pragma unroll
            for (int i = 0; i < 8; i++) {
                float4 p = P4[(ty*8+i)*32 + kk4];
                O[i][0] = fmaf(p.x, vb[0].x, O[i][0]);
                O[i][1] = fmaf(p.x, vb[0].y, O[i][1]);
                O[i][2] = fmaf(p.x, vb[0].z, O[i][2]);
                O[i][3] = fmaf(p.x, vb[0].w, O[i][3]);
                O[i][0] = fmaf(p.y, vb[1].x, O[i][0]);
                O[i][1] = fmaf(p.y, vb[1].y, O[i][1]);
                O[i][2] = fmaf(p.y, vb[1].z, O[i][2]);
                O[i][3] = fmaf(p.y, vb[1].w, O[i][3]);
                O[i][0] = fmaf(p.z, vb[2].x, O[i][0]);
                O[i][1] = fmaf(p.z, vb[2].y, O[i][1]);
                O[i][2] = fmaf(p.z, vb[2].z, O[i][2]);
                O[i][3] = fmaf(p.z, vb[2].w, O[i][3]);
                O[i][0] = fmaf(p.w, vb[3].x, O[i][0]);
                O[i][1] = fmaf(p.w, vb[3].y, O[i][1]);
                O[i][2] = fmaf(p.w, vb[3].z, O[i][2]);
                O[i][3] = fmaf(p.w, vb[3].w, O[i][3]);
            }
        }
    }

    float* Op = g_ao + ((size_t)b*NUM_N + q0)*NUM_C + h*HD;
#pragma unroll
    for (int i = 0; i < 8; i++) {
        float inv = 1.0f / l_i[i];
        *reinterpret_cast<float4*>(&Op[(size_t)(ty*8+i)*NUM_C + tx*4]) =
            make_float4(O[i][0]*inv, O[i][1]*inv, O[i][2]*inv, O[i][3]*inv);
    }
}

// ---------------------------------------------------------------------------
extern "C" void kernel_launch(void* const* d_in, const int* in_sizes, int n_in,
                              void* d_out, int out_size) {
    const float* x       = (const float*)d_in[0];
    const unsigned char* mask = (const unsigned char*)d_in[1];
    const float* w_qkv   = (const float*)d_in[2];
    const float* w_proj  = (const float*)d_in[3];
    const float* b_proj  = (const float*)d_in[4];
    const float* q_gamma = (const float*)d_in[5];
    const float* q_beta  = (const float*)d_in[6];
    const float* k_gamma = (const float*)d_in[7];
    const float* k_beta  = (const float*)d_in[8];
    float* out = (float*)d_out;

    cudaFuncSetAttribute(attn_kernel,  cudaFuncAttributeMaxDynamicSharedMemorySize, ATTN_SMEM);
    cudaFuncSetAttribute(mma_gemm<0>,  cudaFuncAttributeMaxDynamicSharedMemorySize, GEMM_SMEM);
    cudaFuncSetAttribute(mma_gemm<1>,  cudaFuncAttributeMaxDynamicSharedMemorySize, GEMM_SMEM);

    __nv_bfloat16 *xh, *xl, *wqh, *wql, *aoh, *aol, *wph, *wpl;
    float* ao;
    cudaGetSymbolAddress((void**)&xh,  g_xh);  cudaGetSymbolAddress((void**)&xl,  g_xl);
    cudaGetSymbolAddress((void**)&wqh, g_wqh); cudaGetSymbolAddress((void**)&wql, g_wql);
    cudaGetSymbolAddress((void**)&aoh, g_aoh); cudaGetSymbolAddress((void**)&aol, g_aol);
    cudaGetSymbolAddress((void**)&wph, g_wph); cudaGetSymbolAddress((void**)&wpl, g_wpl);
    cudaGetSymbolAddress((void**)&ao,  g_ao);

    // 0) split conversions of GEMM inputs
    const int n4x  = MTOT*NUM_C/4;
    const int n4wq = 3*NUM_C*NUM_C/4;
    const int n4wp = NUM_C*NUM_C/4;
    split_conv<<<(n4x  + 255)/256, 256>>>(x,      xh,  xl,  n4x);
    split_conv<<<(n4wq + 255)/256, 256>>>(w_qkv,  wqh, wql, n4wq);
    split_conv<<<(n4wp + 255)/256, 256>>>(w_proj, wph, wpl, n4wp);

    // 1) QKV GEMM on mma.sync tensor cores (scatter epilogue)
    mma_gemm<0><<<dim3(3*NUM_C/128, MTOT/128), 256, GEMM_SMEM>>>(xh, xl, wqh, wql, nullptr, nullptr);

    // 2) flash attention with fused q/k LayerNorm
    attn_kernel<<<dim3(NUM_N/128, NUM_B*NUM_H), 256, ATTN_SMEM>>>(
        mask, q_gamma, q_beta, k_gamma, k_beta);

    // 2b) split-convert attention output
    split_conv<<<(n4x + 255)/256, 256>>>(ao, aoh, aol, n4x);

    // 3) output projection on mma.sync tensor cores (+bias)
    mma_gemm<1><<<dim3(NUM_C/128, MTOT/128), 256, GEMM_SMEM>>>(aoh, aol, wph, wpl, b_proj, out);
}

// round 14
// speedup vs baseline: 1.4304x; 1.0221x over previous
#include <cuda_runtime.h>
#include <cuda_bf16.h>
#include <cuda_fp16.h>
#include <math.h>
#include <cstdint>

#define NUM_B 2
#define NUM_N 2048
#define NUM_C 1024
#define NUM_H 16
#define HD    64
#define MTOT  (NUM_B*NUM_N)      /* 4096 */

// ---------------------------------------------------------------------------
// Scratch (allocation-free: __device__ globals)
// ---------------------------------------------------------------------------
__device__ float g_q[NUM_B*NUM_H*NUM_N*HD];   // fp32 (LN needs precision)
__device__ float g_k[NUM_B*NUM_H*NUM_N*HD];
__device__ __half g_vh[NUM_B*NUM_H*NUM_N*HD]; // V pre-converted to fp16
__device__ float g_ao[NUM_B*NUM_N*NUM_C];     // attention out, [B,N,C]

// split-bf16 copies (hi/lo) for tensor-core GEMMs
__device__ __nv_bfloat16 g_xh [MTOT*NUM_C];
__device__ __nv_bfloat16 g_xl [MTOT*NUM_C];
__device__ __nv_bfloat16 g_wqh[3*NUM_C*NUM_C];
__device__ __nv_bfloat16 g_wql[3*NUM_C*NUM_C];
__device__ __nv_bfloat16 g_aoh[MTOT*NUM_C];
__device__ __nv_bfloat16 g_aol[MTOT*NUM_C];
__device__ __nv_bfloat16 g_wph[NUM_C*NUM_C];
__device__ __nv_bfloat16 g_wpl[NUM_C*NUM_C];

// ---------------------------------------------------------------------------
// mma.sync helpers (sm_80+ HMMA)
// ---------------------------------------------------------------------------
__device__ __forceinline__ void mma16816(float* d, const uint32_t* a, const uint32_t* b) {
    asm volatile(
        "mma.sync.aligned.m16n8k16.row.col.f32.bf16.bf16.f32 "
        "{%0,%1,%2,%3}, {%4,%5,%6,%7}, {%8,%9}, {%0,%1,%2,%3};"
        : "+f"(d[0]), "+f"(d[1]), "+f"(d[2]), "+f"(d[3])
        : "r"(a[0]), "r"(a[1]), "r"(a[2]), "r"(a[3]), "r"(b[0]), "r"(b[1]));
}
__device__ __forceinline__ void mma16816h(float* d, const uint32_t* a, const uint32_t* b) {
    asm volatile(
        "mma.sync.aligned.m16n8k16.row.col.f32.f16.f16.f32 "
        "{%0,%1,%2,%3}, {%4,%5,%6,%7}, {%8,%9}, {%0,%1,%2,%3};"
        : "+f"(d[0]), "+f"(d[1]), "+f"(d[2]), "+f"(d[3])
        : "r"(a[0]), "r"(a[1]), "r"(a[2]), "r"(a[3]), "r"(b[0]), "r"(b[1]));
}
__device__ __forceinline__ uint32_t lds_u32(const void* p) {
    return *reinterpret_cast<const uint32_t*>(p);
}
__device__ __forceinline__ uint32_t pack_h2(float a, float b) {
    __half2 h = __floats2half2_rn(a, b);
    return *reinterpret_cast<uint32_t*>(&h);
}
__device__ __forceinline__ uint32_t pack_bf2(float a, float b) {
    __nv_bfloat162 h(__float2bfloat16(a), __float2bfloat16(b));
    return *reinterpret_cast<uint32_t*>(&h);
}

// ---------------------------------------------------------------------------
// Kernel 0: fp32 -> (bf16 hi, bf16 lo) split conversion, 4 elems/thread.
// ---------------------------------------------------------------------------
struct __align__(8) bf4 { __nv_bfloat16 a, b, c, d; };

__global__ __launch_bounds__(256) void split_conv(const float* __restrict__ s,
                                                  __nv_bfloat16* __restrict__ hi,
                                                  __nv_bfloat16* __restrict__ lo,
                                                  int n4) {
    int i = blockIdx.x * blockDim.x + threadIdx.x;
    if (i >= n4) return;
    float4 v = reinterpret_cast<const float4*>(s)[i];
    __nv_bfloat16 h0 = __float2bfloat16(v.x);
    __nv_bfloat16 h1 = __float2bfloat16(v.y);
    __nv_bfloat16 h2 = __float2bfloat16(v.z);
    __nv_bfloat16 h3 = __float2bfloat16(v.w);
    __nv_bfloat16 l0 = __float2bfloat16(v.x - __bfloat162float(h0));
    __nv_bfloat16 l1 = __float2bfloat16(v.y - __bfloat162float(h1));
    __nv_bfloat16 l2 = __float2bfloat16(v.z - __bfloat162float(h2));
    __nv_bfloat16 l3 = __float2bfloat16(v.w - __bfloat162float(h3));
    bf4 hh = {h0, h1, h2, h3};
    bf4 ll = {l0, l1, l2, l3};
    reinterpret_cast<bf4*>(hi)[i] = hh;
    reinterpret_cast<bf4*>(lo)[i] = ll;
}

// ---------------------------------------------------------------------------
// Kernel 1/3: mma.sync bf16-split GEMM (as R13).  EPI=0: scatter q/k fp32,
// v as fp16.  EPI=1: out + bias.
// ---------------------------------------------------------------------------
#define LDA 40
#define STAGE_ELE (4*128*LDA)
#define GEMM_SMEM (2*STAGE_ELE*2)

template<int EPI>
__global__ __launch_bounds__(256) void mma_gemm(const __nv_bfloat16* __restrict__ Ah,
                                                const __nv_bfloat16* __restrict__ Al,
                                                const __nv_bfloat16* __restrict__ Bh,
                                                const __nv_bfloat16* __restrict__ Bl,
                                                const float* __restrict__ bias,
                                                float* __restrict__ outp) {
    extern __shared__ __nv_bfloat16 smem[];
    const int tid  = threadIdx.x;
    const int wid  = tid >> 5, lane = tid & 31;
    const int wm   = wid >> 1;
    const int wn   = wid & 1;
    const int g    = lane >> 2;
    const int tg   = lane & 3;
    const int bm   = blockIdx.y * 128;
    const int bn   = blockIdx.x * 128;

    const int lrow = tid >> 1;
    const int lhalf = (tid & 1) * 16;
    const __nv_bfloat16* gah = Ah + (size_t)(bm + lrow) * NUM_C + lhalf;
    const __nv_bfloat16* gal = Al + (size_t)(bm + lrow) * NUM_C + lhalf;
    const __nv_bfloat16* gbh = Bh + (size_t)(bn + lrow) * NUM_C + lhalf;
    const __nv_bfloat16* gbl = Bl + (size_t)(bn + lrow) * NUM_C + lhalf;
    const int soff = lrow * LDA + lhalf;

    float acc[2][8][4];
#pragma unroll
    for (int i = 0; i < 2; i++)
#pragma unroll
        for (int j = 0; j < 8; j++)
#pragma unroll
            for (int t = 0; t < 4; t++) acc[i][j][t] = 0.0f;

    uint4 pr[8];
    pr[0] = *reinterpret_cast<const uint4*>(gah);
    pr[1] = *reinterpret_cast<const uint4*>(gah + 8);
    pr[2] = *reinterpret_cast<const uint4*>(gal);
    pr[3] = *reinterpret_cast<const uint4*>(gal + 8);
    pr[4] = *reinterpret_cast<const uint4*>(gbh);
    pr[5] = *reinterpret_cast<const uint4*>(gbh + 8);
    pr[6] = *reinterpret_cast<const uint4*>(gbl);
    pr[7] = *reinterpret_cast<const uint4*>(gbl + 8);

    for (int c = 0; c < NUM_C/32; c++) {
        const int s = c & 1;
        __nv_bfloat16* st = smem + s * STAGE_ELE;
        __nv_bfloat16* sAh = st;
        __nv_bfloat16* sAl = st + 128*LDA;
        __nv_bfloat16* sBh = st + 2*128*LDA;
        __nv_bfloat16* sBl = st + 3*128*LDA;

        *reinterpret_cast<uint4*>(sAh + soff)     = pr[0];
        *reinterpret_cast<uint4*>(sAh + soff + 8) = pr[1];
        *reinterpret_cast<uint4*>(sAl + soff)     = pr[2];
        *reinterpret_cast<uint4*>(sAl + soff + 8) = pr[3];
        *reinterpret_cast<uint4*>(sBh + soff)     = pr[4];
        *reinterpret_cast<uint4*>(sBh + soff + 8) = pr[5];
        *reinterpret_cast<uint4*>(sBl + soff)     = pr[6];
        *reinterpret_cast<uint4*>(sBl + soff + 8) = pr[7];
        __syncthreads();

        if (c + 1 < NUM_C/32) {
            const int go = (c + 1) * 32;
            pr[0] = *reinterpret_cast<const uint4*>(gah + go);
            pr[1] = *reinterpret_cast<const uint4*>(gah + go + 8);
            pr[2] = *reinterpret_cast<const uint4*>(gal + go);
            pr[3] = *reinterpret_cast<const uint4*>(gal + go + 8);
            pr[4] = *reinterpret_cast<const uint4*>(gbh + go);
            pr[5] = *reinterpret_cast<const uint4*>(gbh + go + 8);
            pr[6] = *reinterpret_cast<const uint4*>(gbl + go);
            pr[7] = *reinterpret_cast<const uint4*>(gbl + go + 8);
        }

#pragma unroll
        for (int ks = 0; ks < 2; ks++) {
            const int kb = ks * 16;
            uint32_t fah[2][4], fal[2][4];
#pragma unroll
            for (int mf = 0; mf < 2; mf++) {
                const int am = wm*32 + mf*16;
                fah[mf][0] = lds_u32(&sAh[(am + g    )*LDA + kb + tg*2]);
                fah[mf][1] = lds_u32(&sAh[(am + g + 8)*LDA + kb + tg*2]);
                fah[mf][2] = lds_u32(&sAh[(am + g    )*LDA + kb + tg*2 + 8]);
                fah[mf][3] = lds_u32(&sAh[(am + g + 8)*LDA + kb + tg*2 + 8]);
                fal[mf][0] = lds_u32(&sAl[(am + g    )*LDA + kb + tg*2]);
                fal[mf][1] = lds_u32(&sAl[(am + g + 8)*LDA + kb + tg*2]);
                fal[mf][2] = lds_u32(&sAl[(am + g    )*LDA + kb + tg*2 + 8]);
                fal[mf][3] = lds_u32(&sAl[(am + g + 8)*LDA + kb + tg*2 + 8]);
            }
#pragma unroll
            for (int nf = 0; nf < 8; nf++) {
                const int bnr = wn*64 + nf*8 + g;
                uint32_t fbh[2], fbl[2];
                fbh[0] = lds_u32(&sBh[bnr*LDA + kb + tg*2]);
                fbh[1] = lds_u32(&sBh[bnr*LDA + kb + tg*2 + 8]);
                fbl[0] = lds_u32(&sBl[bnr*LDA + kb + tg*2]);
                fbl[1] = lds_u32(&sBl[bnr*LDA + kb + tg*2 + 8]);
#pragma unroll
                for (int mf = 0; mf < 2; mf++) {
                    mma16816(acc[mf][nf], fah[mf], fbh);
                    mma16816(acc[mf][nf], fah[mf], fbl);
                    mma16816(acc[mf][nf], fal[mf], fbh);
                }
            }
        }
        __syncthreads();
    }

    if (EPI == 0) {
        const int n0 = bn + wn*64;
        const int which = n0 >> 10;
        const int h = (n0 & 1023) >> 6;
        if (which < 2) {
            float* base = (which == 0) ? g_q : g_k;
#pragma unroll
            for (int mf = 0; mf < 2; mf++) {
#pragma unroll
                for (int half = 0; half < 2; half++) {
                    const int mrow = bm + wm*32 + mf*16 + g + half*8;
                    float* dst = base + (((size_t)((mrow >> 11) * NUM_H + h)) * NUM_N
                                         + (mrow & 2047)) * HD + (n0 & 63);
#pragma unroll
                    for (int nf = 0; nf < 8; nf++) {
                        *reinterpret_cast<float2*>(dst + nf*8 + tg*2) =
                            make_float2(acc[mf][nf][half*2], acc[mf][nf][half*2+1]);
                    }
                }
            }
        } else {
#pragma unroll
            for (int mf = 0; mf < 2; mf++) {
#pragma unroll
                for (int half = 0; half < 2; half++) {
                    const int mrow = bm + wm*32 + mf*16 + g + half*8;
                    __half* dst = g_vh + (((size_t)((mrow >> 11) * NUM_H + h)) * NUM_N
                                          + (mrow & 2047)) * HD + (n0 & 63);
#pragma unroll
                    for (int nf = 0; nf < 8; nf++) {
                        uint32_t p = pack_h2(acc[mf][nf][half*2], acc[mf][nf][half*2+1]);
                        *reinterpret_cast<uint32_t*>(dst + nf*8 + tg*2) = p;
                    }
                }
            }
        }
    } else {
#pragma unroll
        for (int mf = 0; mf < 2; mf++) {
#pragma unroll
            for (int half = 0; half < 2; half++) {
                const int mrow = bm + wm*32 + mf*16 + g + half*8;
                float* dst = outp + (size_t)mrow * NUM_C + bn + wn*64;
#pragma unroll
                for (int nf = 0; nf < 8; nf++) {
                    const int col = bn + wn*64 + nf*8 + tg*2;
                    *reinterpret_cast<float2*>(dst + nf*8 + tg*2) =
                        make_float2(acc[mf][nf][half*2] + bias[col],
                                    acc[mf][nf][half*2+1] + bias[col+1]);
                }
            }
        }
    }
}

// ---------------------------------------------------------------------------
// Kernel 2: tensor-core flash attention, fused q/k LayerNorm.
// Block = 128 q of one (b,h), 256 thr = 8 warps, warp tile 16q x 128k.
// S = QK^T: 3-term bf16 split (LN'd q/k in smem as hi/lo).
// P*V: fp16 (FA2 register-fragment trick, V^T fp16 in smem).
// ---------------------------------------------------------------------------
#define LDQ 72     /* bf16 row stride for Q/K tiles (64 + 8 pad) */
#define LDV 136    /* half row stride for V^T (128 + 8 pad)     */
#define ATTN_SMEM (4*128*LDQ*2 + 64*LDV*2)   /* 91136 B */

__global__ __launch_bounds__(256) void attn_kernel(const unsigned char* __restrict__ mask,
                                                   const float* __restrict__ q_gamma,
                                                   const float* __restrict__ q_beta,
                                                   const float* __restrict__ k_gamma,
                                                   const float* __restrict__ k_beta) {
    extern __shared__ char asmem[];
    __nv_bfloat16* Qh = reinterpret_cast<__nv_bfloat16*>(asmem);
    __nv_bfloat16* Ql = Qh + 128*LDQ;
    __nv_bfloat16* Kh = Ql + 128*LDQ;
    __nv_bfloat16* Kl = Kh + 128*LDQ;
    __half*        Vt = reinterpret_cast<__half*>(Kl + 128*LDQ);

    const int bh = blockIdx.y;
    const int b  = bh >> 4;
    const int h  = bh & 15;
    const int q0 = blockIdx.x * 128;

    const float*  Qp = g_q  + ((size_t)bh*NUM_N + q0)*HD;
    const float*  Kp = g_k  + (size_t)bh*NUM_N*HD;
    const __half* Vp = g_vh + (size_t)bh*NUM_N*HD;
    const unsigned char* mp = mask + (size_t)b*NUM_N*NUM_N + (size_t)q0*NUM_N;

    const int tid  = threadIdx.x;
    const int wid  = tid >> 5, lane = tid & 31;
    const int g    = lane >> 2;
    const int tg   = lane & 3;
    const int wq   = wid * 16;

    const int lr = tid >> 1;
    const int d0 = (tid & 1) * 32;

    // ---- Q tile: LayerNorm (+0.125 scale) -> bf16 hi/lo in smem ----
    {
        const float* src = Qp + (size_t)lr*HD + d0;
        float x[32];
        float s = 0.f, ss = 0.f;
#pragma unroll
        for (int j = 0; j < 8; j++) {
            float4 v = *reinterpret_cast<const float4*>(src + j*4);
            x[j*4+0] = v.x; x[j*4+1] = v.y; x[j*4+2] = v.z; x[j*4+3] = v.w;
            s  += v.x + v.y + v.z + v.w;
            ss += v.x*v.x + v.y*v.y + v.z*v.z + v.w*v.w;
        }
        s  += __shfl_xor_sync(0xffffffffu, s,  1);
        ss += __shfl_xor_sync(0xffffffffu, ss, 1);
        float mu  = s * (1.0f/64.0f);
        float var = ss * (1.0f/64.0f) - mu*mu;
        float inv = rsqrtf(var + 1e-5f) * 0.125f;
#pragma unroll
        for (int j = 0; j < 32; j += 2) {
            float a0 = (x[j]   - mu)*inv*q_gamma[d0+j]   + q_beta[d0+j]*0.125f;
            float a1 = (x[j+1] - mu)*inv*q_gamma[d0+j+1] + q_beta[d0+j+1]*0.125f;
            uint32_t hh = pack_bf2(a0, a1);
            __nv_bfloat162 hv = *reinterpret_cast<__nv_bfloat162*>(&hh);
            float r0 = a0 - __bfloat162float(hv.x);
            float r1 = a1 - __bfloat162float(hv.y);
            *reinterpret_cast<uint32_t*>(&Qh[lr*LDQ + d0 + j]) = hh;
            *reinterpret_cast<uint32_t*>(&Ql[lr*LDQ + d0 + j]) = pack_bf2(r0, r1);
        }
    }

    float m_i[2], l_i[2];
    float O[8][4];
    m_i[0] = m_i[1] = -3.402823466e38f;
    l_i[0] = l_i[1] = 0.0f;
#pragma unroll
    for (int dn = 0; dn < 8; dn++)
#pragma unroll
        for (int t = 0; t < 4; t++) O[dn][t] = 0.0f;

    for (int kt = 0; kt < NUM_N/128; kt++) {
        const int k0 = kt * 128;
        __syncthreads();

        // ---- K tile: LayerNorm -> bf16 hi/lo ----
        {
            const float* src = Kp + (size_t)(k0 + lr)*HD + d0;
            float x[32];
            float s = 0.f, ss = 0.f;
#pragma unroll
            for (int j = 0; j < 8; j++) {
                float4 v = *reinterpret_cast<const float4*>(src + j*4);
                x[j*4+0] = v.x; x[j*4+1] = v.y; x[j*4+2] = v.z; x[j*4+3] = v.w;
                s  += v.x + v.y + v.z + v.w;
                ss += v.x*v.x + v.y*v.y + v.z*v.z + v.w*v.w;
            }
            s  += __shfl_xor_sync(0xffffffffu, s,  1);
            ss += __shfl_xor_sync(0xffffffffu, ss, 1);
            float mu  = s * (1.0f/64.0f);
            float var = ss * (1.0f/64.0f) - mu*mu;
            float inv = rsqrtf(var + 1e-5f);
#pragma unroll
            for (int j = 0; j < 32; j += 2) {
                float a0 = (x[j]   - mu)*inv*k_gamma[d0+j]   + k_beta[d0+j];
                float a1 = (x[j+1] - mu)*inv*k_gamma[d0+j+1] + k_beta[d0+j+1];
                uint32_t hh = pack_bf2(a0, a1);
                __nv_bfloat162 hv = *reinterpret_cast<__nv_bfloat162*>(&hh);
                float r0 = a0 - __bfloat162float(hv.x);
                float r1 = a1 - __bfloat162float(hv.y);
                *reinterpret_cast<uint32_t*>(&Kh[lr*LDQ + d0 + j]) = hh;
                *reinterpret_cast<uint32_t*>(&Kl[lr*LDQ + d0 + j]) = pack_bf2(r0, r1);
            }
        }

        // ---- V tile: fp16 transpose into Vt[d][k] ----
        {
            union { uint4 u[4]; __half hh[32]; } vv;
            const uint4* vrow = reinterpret_cast<const uint4*>(Vp + (size_t)(k0 + lr)*HD + d0);
#pragma unroll
            for (int j = 0; j < 4; j++) vv.u[j] = vrow[j];
#pragma unroll
            for (int j = 0; j < 32; j++) Vt[(d0 + j)*LDV + lr] = vv.hh[j];
        }
        __syncthreads();

        // ---- S = Q*K^T : warp 16q x 128k, 3-term bf16 split ----
        float S[16][4];
#pragma unroll
        for (int nf = 0; nf < 16; nf++)
#pragma unroll
            for (int t = 0; t < 4; t++) S[nf][t] = 0.0f;

#pragma unroll
        for (int ks = 0; ks < 4; ks++) {
            const int kb = ks * 16;
            uint32_t ah[4], al[4];
            ah[0] = lds_u32(&Qh[(wq + g    )*LDQ + kb + tg*2]);
            ah[1] = lds_u32(&Qh[(wq + g + 8)*LDQ + kb + tg*2]);
            ah[2] = lds_u32(&Qh[(wq + g    )*LDQ + kb + tg*2 + 8]);
            ah[3] = lds_u32(&Qh[(wq + g + 8)*LDQ + kb + tg*2 + 8]);
            al[0] = lds_u32(&Ql[(wq + g    )*LDQ + kb + tg*2]);
            al[1] = lds_u32(&Ql[(wq + g + 8)*LDQ + kb + tg*2]);
            al[2] = lds_u32(&Ql[(wq + g    )*LDQ + kb + tg*2 + 8]);
            al[3] = lds_u32(&Ql[(wq + g + 8)*LDQ + kb + tg*2 + 8]);
#pragma unroll
            for (int nf = 0; nf < 16; nf++) {
                const int kr = nf*8 + g;
                uint32_t bhh[2], bll[2];
                bhh[0] = lds_u32(&Kh[kr*LDQ + kb + tg*2]);
                bhh[1] = lds_u32(&Kh[kr*LDQ + kb + tg*2 + 8]);
                bll[0] = lds_u32(&Kl[kr*LDQ + kb + tg*2]);
                bll[1] = lds_u32(&Kl[kr*LDQ + kb + tg*2 + 8]);
                mma16816(S[nf], ah, bhh);
                mma16816(S[nf], ah, bll);
                mma16816(S[nf], al, bhh);
            }
        }

        // ---- mask + online softmax (rows wq+g, wq+g+8) ----
        {
            const unsigned char* m0p = mp + (size_t)(wq + g)*NUM_N + k0;
            const unsigned char* m1p = m0p + 8*NUM_N;
#pragma unroll
            for (int nf = 0; nf < 16; nf++) {
                const int cb = nf*8 + tg*2;
                uchar2 ma = *reinterpret_cast<const uchar2*>(m0p + cb);
                uchar2 mb = *reinterpret_cast<const uchar2*>(m1p + cb);
                if (ma.x) S[nf][0] = -3.402823466e38f;
                if (ma.y) S[nf][1] = -3.402823466e38f;
                if (mb.x) S[nf][2] = -3.402823466e38f;
                if (mb.y) S[nf][3] = -3.402823466e38f;
            }
            float rm0 = S[0][0], rm1 = S[0][2];
#pragma unroll
            for (int nf = 0; nf < 16; nf++) {
                rm0 = fmaxf(rm0, fmaxf(S[nf][0], S[nf][1]));
                rm1 = fmaxf(rm1, fmaxf(S[nf][2], S[nf][3]));
            }
            rm0 = fmaxf(rm0, __shfl_xor_sync(0xffffffffu, rm0, 1));
            rm0 = fmaxf(rm0, __shfl_xor_sync(0xffffffffu, rm0, 2));
            rm1 = fmaxf(rm1, __shfl_xor_sync(0xffffffffu, rm1, 1));
            rm1 = fmaxf(rm1, __shfl_xor_sync(0xffffffffu, rm1, 2));
            float mn0 = fmaxf(m_i[0], rm0);
            float mn1 = fmaxf(m_i[1], rm1);
            float al0 = __expf(m_i[0] - mn0);
            float al1 = __expf(m_i[1] - mn1);
            float ps0 = 0.f, ps1 = 0.f;
#pragma unroll
            for (int nf = 0; nf < 16; nf++) {
                S[nf][0] = __expf(S[nf][0] - mn0);
                S[nf][1] = __expf(S[nf][1] - mn0);
                S[nf][2] = __expf(S[nf][2] - mn1);
                S[nf][3] = __expf(S[nf][3] - mn1);
                ps0 += S[nf][0] + S[nf][1];
                ps1 += S[nf][2] + S[nf][3];
            }
            ps0 += __shfl_xor_sync(0xffffffffu, ps0, 1);
            ps0 += __shfl_xor_sync(0xffffffffu, ps0, 2);
            ps1 += __shfl_xor_sync(0xffffffffu, ps1, 1);
            ps1 += __shfl_xor_sync(0xffffffffu, ps1, 2);
            l_i[0] = l_i[0]*al0 + ps0;
            l_i[1] = l_i[1]*al1 + ps1;
            m_i[0] = mn0; m_i[1] = mn1;
#pragma unroll
            for (int dn = 0; dn < 8; dn++) {
                O[dn][0] *= al0; O[dn][1] *= al0;
                O[dn][2] *= al1; O[dn][3] *= al1;
            }
        }

        // ---- O += P*V : P stays in registers (FA2 trick), V^T fp16 smem ----
#pragma unroll
        for (int ks = 0; ks < 8; ks++) {
            uint32_t pa[4];
            pa[0] = pack_h2(S[2*ks  ][0], S[2*ks  ][1]);
            pa[1] = pack_h2(S[2*ks  ][2], S[2*ks  ][3]);
            pa[2] = pack_h2(S[2*ks+1][0], S[2*ks+1][1]);
            pa[3] = pack_h2(S[2*ks+1][2], S[2*ks+1][3]);
#pragma unroll
            for (int dn = 0; dn < 8; dn++) {
                uint32_t bb[2];
                bb[0] = lds_u32(&Vt[(dn*8 + g)*LDV + ks*16 + tg*2]);
                bb[1] = lds_u32(&Vt[(dn*8 + g)*LDV + ks*16 + tg*2 + 8]);
                mma16816h(O[dn], pa, bb);
            }
        }
    }

    // ---- epilogue: normalize + write [B,N,C] head-concat ----
    {
        float inv0 = 1.0f / l_i[0];
        float inv1 = 1.0f / l_i[1];
        float* Op = g_ao + ((size_t)b*NUM_N + q0 + wq)*NUM_C + h*HD;
#pragma unroll
        for (int dn = 0; dn < 8; dn++) {
            const int c = dn*8 + tg*2;
            *reinterpret_cast<float2*>(&Op[(size_t)g*NUM_C + c]) =
                make_float2(O[dn][0]*inv0, O[dn][1]*inv0);
            *reinterpret_cast<float2*>(&Op[(size_t)(g+8)*NUM_C + c]) =
                make_float2(O[dn][2]*inv1, O[dn][3]*inv1);
        }
    }
}

// ---------------------------------------------------------------------------
extern "C" void kernel_launch(void* const* d_in, const int* in_sizes, int n_in,
                              void* d_out, int out_size) {
    const float* x       = (const float*)d_in[0];
    const unsigned char* mask = (const unsigned char*)d_in[1];
    const float* w_qkv   = (const float*)d_in[2];
    const float* w_proj  = (const float*)d_in[3];
    const float* b_proj  = (const float*)d_in[4];
    const float* q_gamma = (const float*)d_in[5];
    const float* q_beta  = (const float*)d_in[6];
    const float* k_gamma = (const float*)d_in[7];
    const float* k_beta  = (const float*)d_in[8];
    float* out = (float*)d_out;

    cudaFuncSetAttribute(attn_kernel,  cudaFuncAttributeMaxDynamicSharedMemorySize, ATTN_SMEM);
    cudaFuncSetAttribute(mma_gemm<0>,  cudaFuncAttributeMaxDynamicSharedMemorySize, GEMM_SMEM);
    cudaFuncSetAttribute(mma_gemm<1>,  cudaFuncAttributeMaxDynamicSharedMemorySize, GEMM_SMEM);

    __nv_bfloat16 *xh, *xl, *wqh, *wql, *aoh, *aol, *wph, *wpl;
    float* ao;
    cudaGetSymbolAddress((void**)&xh,  g_xh);  cudaGetSymbolAddress((void**)&xl,  g_xl);
    cudaGetSymbolAddress((void**)&wqh, g_wqh); cudaGetSymbolAddress((void**)&wql, g_wql);
    cudaGetSymbolAddress((void**)&aoh, g_aoh); cudaGetSymbolAddress((void**)&aol, g_aol);
    cudaGetSymbolAddress((void**)&wph, g_wph); cudaGetSymbolAddress((void**)&wpl, g_wpl);
    cudaGetSymbolAddress((void**)&ao,  g_ao);

    const int n4x  = MTOT*NUM_C/4;
    const int n4wq = 3*NUM_C*NUM_C/4;
    const int n4wp = NUM_C*NUM_C/4;
    split_conv<<<(n4x  + 255)/256, 256>>>(x,      xh,  xl,  n4x);
    split_conv<<<(n4wq + 255)/256, 256>>>(w_qkv,  wqh, wql, n4wq);
    split_conv<<<(n4wp + 255)/256, 256>>>(w_proj, wph, wpl, n4wp);

    // 1) QKV GEMM on tensor cores (q/k fp32, v fp16 epilogue)
    mma_gemm<0><<<dim3(3*NUM_C/128, MTOT/128), 256, GEMM_SMEM>>>(xh, xl, wqh, wql, nullptr, nullptr);

    // 2) tensor-core flash attention with fused q/k LayerNorm
    attn_kernel<<<dim3(NUM_N/128, NUM_B*NUM_H), 256, ATTN_SMEM>>>(
        mask, q_gamma, q_beta, k_gamma, k_beta);

    // 2b) split-convert attention output
    split_conv<<<(n4x + 255)/256, 256>>>(ao, aoh, aol, n4x);

    // 3) output projection on tensor cores (+bias)
    mma_gemm<1><<<dim3(NUM_C/128, MTOT/128), 256, GEMM_SMEM>>>(aoh, aol, wph, wpl, b_proj, out);
}

// round 15
// speedup vs baseline: 2.6457x; 1.8496x over previous
#include <cuda_runtime.h>
#include <cuda_bf16.h>
#include <cuda_fp16.h>
#include <math.h>
#include <cstdint>

#define NUM_B 2
#define NUM_N 2048
#define NUM_C 1024
#define NUM_H 16
#define HD    64
#define MTOT  (NUM_B*NUM_N)      /* 4096 */

// ---------------------------------------------------------------------------
// Scratch (allocation-free: __device__ globals)
// ---------------------------------------------------------------------------
__device__ float  g_q [NUM_B*NUM_H*NUM_N*HD];  // fp32 (LN needs precision)
__device__ float  g_k [NUM_B*NUM_H*NUM_N*HD];
__device__ __half g_vh[NUM_B*NUM_H*NUM_N*HD];  // V pre-converted to fp16

// split-bf16 copies (hi/lo) for tensor-core GEMMs
__device__ __nv_bfloat16 g_xh [MTOT*NUM_C];
__device__ __nv_bfloat16 g_xl [MTOT*NUM_C];
__device__ __nv_bfloat16 g_wqh[3*NUM_C*NUM_C];
__device__ __nv_bfloat16 g_wql[3*NUM_C*NUM_C];
__device__ __nv_bfloat16 g_aoh[MTOT*NUM_C];    // attention out hi/lo (written by attn)
__device__ __nv_bfloat16 g_aol[MTOT*NUM_C];
__device__ __nv_bfloat16 g_wph[NUM_C*NUM_C];
__device__ __nv_bfloat16 g_wpl[NUM_C*NUM_C];

// ---------------------------------------------------------------------------
// PTX helpers
// ---------------------------------------------------------------------------
__device__ __forceinline__ uint32_t smem_to_u32(const void* p) {
    uint32_t a;
    asm("{ .reg .u64 t; cvta.to.shared.u64 t, %1; cvt.u32.u64 %0, t; }" : "=r"(a) : "l"(p));
    return a;
}
__device__ __forceinline__ void mma16816(float* d, const uint32_t* a, const uint32_t* b) {
    asm volatile(
        "mma.sync.aligned.m16n8k16.row.col.f32.bf16.bf16.f32 "
        "{%0,%1,%2,%3}, {%4,%5,%6,%7}, {%8,%9}, {%0,%1,%2,%3};"
        : "+f"(d[0]), "+f"(d[1]), "+f"(d[2]), "+f"(d[3])
        : "r"(a[0]), "r"(a[1]), "r"(a[2]), "r"(a[3]), "r"(b[0]), "r"(b[1]));
}
__device__ __forceinline__ void mma16816h(float* d, const uint32_t* a, const uint32_t* b) {
    asm volatile(
        "mma.sync.aligned.m16n8k16.row.col.f32.f16.f16.f32 "
        "{%0,%1,%2,%3}, {%4,%5,%6,%7}, {%8,%9}, {%0,%1,%2,%3};"
        : "+f"(d[0]), "+f"(d[1]), "+f"(d[2]), "+f"(d[3])
        : "r"(a[0]), "r"(a[1]), "r"(a[2]), "r"(a[3]), "r"(b[0]), "r"(b[1]));
}
__device__ __forceinline__ void ldsm4(uint32_t* r, uint32_t a) {
    asm volatile("ldmatrix.sync.aligned.m8n8.x4.shared.b16 {%0,%1,%2,%3}, [%4];"
        : "=r"(r[0]), "=r"(r[1]), "=r"(r[2]), "=r"(r[3]) : "r"(a));
}
#define CP16(dst, src) \
    asm volatile("cp.async.cg.shared.global [%0], [%1], 16;" :: "r"(dst), "l"(src))
#define CP_COMMIT() asm volatile("cp.async.commit_group;" ::: "memory")
#define CP_WAIT(n)  asm volatile("cp.async.wait_group %0;" :: "n"(n) : "memory")

__device__ __forceinline__ uint32_t pack_h2(float a, float b) {
    __half2 h = __floats2half2_rn(a, b);
    return *reinterpret_cast<uint32_t*>(&h);
}
__device__ __forceinline__ uint32_t pack_bf2(float a, float b) {
    __nv_bfloat162 h(__float2bfloat16(a), __float2bfloat16(b));
    return *reinterpret_cast<uint32_t*>(&h);
}

// ---------------------------------------------------------------------------
// Kernel 0: fp32 -> (bf16 hi, bf16 lo) split conversion, 4 elems/thread.
// ---------------------------------------------------------------------------
struct __align__(8) bf4 { __nv_bfloat16 a, b, c, d; };

__global__ __launch_bounds__(256) void split_conv(const float* __restrict__ s,
                                                  __nv_bfloat16* __restrict__ hi,
                                                  __nv_bfloat16* __restrict__ lo,
                                                  int n4) {
    int i = blockIdx.x * blockDim.x + threadIdx.x;
    if (i >= n4) return;
    float4 v = reinterpret_cast<const float4*>(s)[i];
    __nv_bfloat16 h0 = __float2bfloat16(v.x);
    __nv_bfloat16 h1 = __float2bfloat16(v.y);
    __nv_bfloat16 h2 = __float2bfloat16(v.z);
    __nv_bfloat16 h3 = __float2bfloat16(v.w);
    __nv_bfloat16 l0 = __float2bfloat16(v.x - __bfloat162float(h0));
    __nv_bfloat16 l1 = __float2bfloat16(v.y - __bfloat162float(h1));
    __nv_bfloat16 l2 = __float2bfloat16(v.z - __bfloat162float(h2));
    __nv_bfloat16 l3 = __float2bfloat16(v.w - __bfloat162float(h3));
    bf4 hh = {h0, h1, h2, h3};
    bf4 ll = {l0, l1, l2, l3};
    reinterpret_cast<bf4*>(hi)[i] = hh;
    reinterpret_cast<bf4*>(lo)[i] = ll;
}

// ---------------------------------------------------------------------------
// Kernel 1/3: mma.sync bf16-split GEMM.  D[m,n] = sum_k A[m,k]*B[n,k]  (NT)
// Block 128x128, BK=32, 8 warps (4m x 2n), warp tile 32m x 64n.
// cp.async double-buffer + ldmatrix fragment loads.  2 CTAs/SM.
// EPI=0: scatter q/k fp32, v fp16.  EPI=1: out + bias.
// ---------------------------------------------------------------------------
#define LDA 40
#define ARR_B   (128*LDA*2)       /* 10240 B per operand array */
#define STAGE_B (4*ARR_B)         /* 40960 B per stage */
#define GEMM_SMEM (2*STAGE_B)     /* 81920 B */

template<int EPI>
__global__ __launch_bounds__(256, 2) void mma_gemm(const __nv_bfloat16* __restrict__ Ah,
                                                   const __nv_bfloat16* __restrict__ Al,
                                                   const __nv_bfloat16* __restrict__ Bh,
                                                   const __nv_bfloat16* __restrict__ Bl,
                                                   const float* __restrict__ bias,
                                                   float* __restrict__ outp) {
    extern __shared__ __nv_bfloat16 smem[];
    const uint32_t sb = smem_to_u32(smem);
    const int tid  = threadIdx.x;
    const int wid  = tid >> 5, lane = tid & 31;
    const int wm   = wid >> 1;            // 0..3
    const int wn   = wid & 1;             // 0..1
    const int g    = lane >> 2;
    const int tg   = lane & 3;
    const int bm   = blockIdx.y * 128;
    const int bn   = blockIdx.x * 128;

    // loader: 2 threads per row, 32 bf16 each (2 x 16B cp.async per array)
    const int lrow  = tid >> 1;
    const int lhalf = (tid & 1) * 16;
    const __nv_bfloat16* gah = Ah + (size_t)(bm + lrow) * NUM_C + lhalf;
    const __nv_bfloat16* gal = Al + (size_t)(bm + lrow) * NUM_C + lhalf;
    const __nv_bfloat16* gbh = Bh + (size_t)(bn + lrow) * NUM_C + lhalf;
    const __nv_bfloat16* gbl = Bl + (size_t)(bn + lrow) * NUM_C + lhalf;
    const uint32_t dstA = sb + (uint32_t)(lrow * LDA + lhalf) * 2;

#define GISSUE(s, c) do {                                                      \
        uint32_t _d = dstA + (uint32_t)(s) * STAGE_B;                          \
        const int _go = (c) * 32;                                              \
        CP16(_d,               gah + _go); CP16(_d + 16,           gah + _go + 8); \
        CP16(_d +   ARR_B,     gal + _go); CP16(_d +   ARR_B + 16, gal + _go + 8); \
        CP16(_d + 2*ARR_B,     gbh + _go); CP16(_d + 2*ARR_B + 16, gbh + _go + 8); \
        CP16(_d + 3*ARR_B,     gbl + _go); CP16(_d + 3*ARR_B + 16, gbl + _go + 8); \
    } while (0)

    // ldmatrix lane address components
    const uint32_t arow = (uint32_t)(wm*32 + ((lane>>3)&1)*8 + (lane&7));
    const uint32_t acol = (uint32_t)((lane>>4)*8);
    const uint32_t brow = (uint32_t)(wn*64 + ((lane>>4)&1)*8 + (lane&7));
    const uint32_t bcol = (uint32_t)(((lane>>3)&1)*8);

    float acc[2][8][4];
#pragma unroll
    for (int i = 0; i < 2; i++)
#pragma unroll
        for (int j = 0; j < 8; j++)
#pragma unroll
            for (int t = 0; t < 4; t++) acc[i][j][t] = 0.0f;

    GISSUE(0, 0);
    CP_COMMIT();

    for (int c = 0; c < NUM_C/32; c++) {
        if (c + 1 < NUM_C/32) {
            GISSUE((c + 1) & 1, c + 1);
            CP_COMMIT();
            CP_WAIT(1);
        } else {
            CP_WAIT(0);
        }
        __syncthreads();

        const uint32_t stB = sb + (uint32_t)(c & 1) * STAGE_B;
#pragma unroll
        for (int ks = 0; ks < 2; ks++) {
            const uint32_t kb = ks * 16;
            uint32_t fah[2][4], fal[2][4];
#pragma unroll
            for (int mf = 0; mf < 2; mf++) {
                const uint32_t ao = ((arow + mf*16) * LDA + kb + acol) * 2;
                ldsm4(fah[mf], stB + ao);
                ldsm4(fal[mf], stB + ARR_B + ao);
            }
#pragma unroll
            for (int p = 0; p < 4; p++) {
                const uint32_t bo = ((brow + p*16) * LDA + kb + bcol) * 2;
                uint32_t bh4[4], bl4[4];
                ldsm4(bh4, stB + 2*ARR_B + bo);
                ldsm4(bl4, stB + 3*ARR_B + bo);
#pragma unroll
                for (int mf = 0; mf < 2; mf++) {
                    mma16816(acc[mf][2*p],   fah[mf], bh4);
                    mma16816(acc[mf][2*p],   fah[mf], bl4);
                    mma16816(acc[mf][2*p],   fal[mf], bh4);
                    mma16816(acc[mf][2*p+1], fah[mf], bh4 + 2);
                    mma16816(acc[mf][2*p+1], fah[mf], bl4 + 2);
                    mma16816(acc[mf][2*p+1], fal[mf], bh4 + 2);
                }
            }
        }
        __syncthreads();
    }
#undef GISSUE

    // epilogue.  D row = bm + wm*32 + mf*16 + g (+8), col = bn + wn*64 + nf*8 + tg*2
    if (EPI == 0) {
        const int n0 = bn + wn*64;
        const int which = n0 >> 10;
        const int h = (n0 & 1023) >> 6;
        if (which < 2) {
            float* base = (which == 0) ? g_q : g_k;
#pragma unroll
            for (int mf = 0; mf < 2; mf++) {
#pragma unroll
                for (int half = 0; half < 2; half++) {
                    const int mrow = bm + wm*32 + mf*16 + g + half*8;
                    float* dst = base + (((size_t)((mrow >> 11) * NUM_H + h)) * NUM_N
                                         + (mrow & 2047)) * HD + (n0 & 63);
#pragma unroll
                    for (int nf = 0; nf < 8; nf++) {
                        *reinterpret_cast<float2*>(dst + nf*8 + tg*2) =
                            make_float2(acc[mf][nf][half*2], acc[mf][nf][half*2+1]);
                    }
                }
            }
        } else {
#pragma unroll
            for (int mf = 0; mf < 2; mf++) {
#pragma unroll
                for (int half = 0; half < 2; half++) {
                    const int mrow = bm + wm*32 + mf*16 + g + half*8;
                    __half* dst = g_vh + (((size_t)((mrow >> 11) * NUM_H + h)) * NUM_N
                                          + (mrow & 2047)) * HD + (n0 & 63);
#pragma unroll
                    for (int nf = 0; nf < 8; nf++) {
                        *reinterpret_cast<uint32_t*>(dst + nf*8 + tg*2) =
                            pack_h2(acc[mf][nf][half*2], acc[mf][nf][half*2+1]);
                    }
                }
            }
        }
    } else {
#pragma unroll
        for (int mf = 0; mf < 2; mf++) {
#pragma unroll
            for (int half = 0; half < 2; half++) {
                const int mrow = bm + wm*32 + mf*16 + g + half*8;
                float* dst = outp + (size_t)mrow * NUM_C + bn + wn*64;
#pragma unroll
                for (int nf = 0; nf < 8; nf++) {
                    const int col = bn + wn*64 + nf*8 + tg*2;
                    *reinterpret_cast<float2*>(dst + nf*8 + tg*2) =
                        make_float2(acc[mf][nf][half*2] + bias[col],
                                    acc[mf][nf][half*2+1] + bias[col+1]);
                }
            }
        }
    }
}

// ---------------------------------------------------------------------------
// Kernel 2: tensor-core flash attention, fused q/k LayerNorm.
// Block = 128 q of one (b,h), 8 warps, warp tile 16q x 128k.
// S = QK^T: 3-term bf16 split via ldmatrix.  P*V: fp16, P from registers.
// Epilogue writes bf16 hi/lo split directly (feeds proj GEMM).
// ---------------------------------------------------------------------------
#define LDQ 72     /* bf16 row stride for Q/K tiles */
#define LDV 136    /* half row stride for V^T       */
#define OFF_QH 0
#define OFF_QL (128*LDQ*2)
#define OFF_KH (2*128*LDQ*2)
#define OFF_KL (3*128*LDQ*2)
#define OFF_VT (4*128*LDQ*2)
#define ATTN_SMEM (4*128*LDQ*2 + 64*LDV*2)   /* 91136 B */

__global__ __launch_bounds__(256) void attn_kernel(const unsigned char* __restrict__ mask,
                                                   const float* __restrict__ q_gamma,
                                                   const float* __restrict__ q_beta,
                                                   const float* __restrict__ k_gamma,
                                                   const float* __restrict__ k_beta) {
    extern __shared__ char asmem[];
    __nv_bfloat16* Qh = reinterpret_cast<__nv_bfloat16*>(asmem);
    __nv_bfloat16* Ql = Qh + 128*LDQ;
    __nv_bfloat16* Kh = Ql + 128*LDQ;
    __nv_bfloat16* Kl = Kh + 128*LDQ;
    __half*        Vt = reinterpret_cast<__half*>(Kl + 128*LDQ);
    const uint32_t sb = smem_to_u32(asmem);

    const int bh = blockIdx.y;
    const int b  = bh >> 4;
    const int h  = bh & 15;
    const int q0 = blockIdx.x * 128;

    const float*  Qp = g_q  + ((size_t)bh*NUM_N + q0)*HD;
    const float*  Kp = g_k  + (size_t)bh*NUM_N*HD;
    const __half* Vp = g_vh + (size_t)bh*NUM_N*HD;
    const unsigned char* mp = mask + (size_t)b*NUM_N*NUM_N + (size_t)q0*NUM_N;

    const int tid  = threadIdx.x;
    const int wid  = tid >> 5, lane = tid & 31;
    const int g    = lane >> 2;
    const int tg   = lane & 3;
    const int wq   = wid * 16;

    const int lr = tid >> 1;
    const int d0 = (tid & 1) * 32;

    // ldmatrix lane address components
    const uint32_t aq_row = (uint32_t)(wq + ((lane>>3)&1)*8 + (lane&7));
    const uint32_t aq_col = (uint32_t)((lane>>4)*8);
    const uint32_t b_row  = (uint32_t)(((lane>>4)&1)*8 + (lane&7));
    const uint32_t b_col  = (uint32_t)(((lane>>3)&1)*8);

    // ---- Q tile: LayerNorm (+0.125 scale) -> bf16 hi/lo in smem ----
    {
        const float* src = Qp + (size_t)lr*HD + d0;
        float x[32];
        float s = 0.f, ss = 0.f;
#pragma unroll
        for (int j = 0; j < 8; j++) {
            float4 v = *reinterpret_cast<const float4*>(src + j*4);
            x[j*4+0] = v.x; x[j*4+1] = v.y; x[j*4+2] = v.z; x[j*4+3] = v.w;
            s  += v.x + v.y + v.z + v.w;
            ss += v.x*v.x + v.y*v.y + v.z*v.z + v.w*v.w;
        }
        s  += __shfl_xor_sync(0xffffffffu, s,  1);
        ss += __shfl_xor_sync(0xffffffffu, ss, 1);
        float mu  = s * (1.0f/64.0f);
        float var = ss * (1.0f/64.0f) - mu*mu;
        float inv = rsqrtf(var + 1e-5f) * 0.125f;
#pragma unroll
        for (int j = 0; j < 32; j += 2) {
            float a0 = (x[j]   - mu)*inv*q_gamma[d0+j]   + q_beta[d0+j]*0.125f;
            float a1 = (x[j+1] - mu)*inv*q_gamma[d0+j+1] + q_beta[d0+j+1]*0.125f;
            uint32_t hh = pack_bf2(a0, a1);
            __nv_bfloat162 hv = *reinterpret_cast<__nv_bfloat162*>(&hh);
            *reinterpret_cast<uint32_t*>(&Qh[lr*LDQ + d0 + j]) = hh;
            *reinterpret_cast<uint32_t*>(&Ql[lr*LDQ + d0 + j]) =
                pack_bf2(a0 - __bfloat162float(hv.x), a1 - __bfloat162float(hv.y));
        }
    }

    float m_i[2], l_i[2];
    float O[8][4];
    m_i[0] = m_i[1] = -3.402823466e38f;
    l_i[0] = l_i[1] = 0.0f;
#pragma unroll
    for (int dn = 0; dn < 8; dn++)
#pragma unroll
        for (int t = 0; t < 4; t++) O[dn][t] = 0.0f;

    for (int kt = 0; kt < NUM_N/128; kt++) {
        const int k0 = kt * 128;
        __syncthreads();

        // ---- K tile: LayerNorm -> bf16 hi/lo ----
        {
            const float* src = Kp + (size_t)(k0 + lr)*HD + d0;
            float x[32];
            float s = 0.f, ss = 0.f;
#pragma unroll
            for (int j = 0; j < 8; j++) {
                float4 v = *reinterpret_cast<const float4*>(src + j*4);
                x[j*4+0] = v.x; x[j*4+1] = v.y; x[j*4+2] = v.z; x[j*4+3] = v.w;
                s  += v.x + v.y + v.z + v.w;
                ss += v.x*v.x + v.y*v.y + v.z*v.z + v.w*v.w;
            }
            s  += __shfl_xor_sync(0xffffffffu, s,  1);
            ss += __shfl_xor_sync(0xffffffffu, ss, 1);
            float mu  = s * (1.0f/64.0f);
            float var = ss * (1.0f/64.0f) - mu*mu;
            float inv = rsqrtf(var + 1e-5f);
#pragma unroll
            for (int j = 0; j < 32; j += 2) {
                float a0 = (x[j]   - mu)*inv*k_gamma[d0+j]   + k_beta[d0+j];
                float a1 = (x[j+1] - mu)*inv*k_gamma[d0+j+1] + k_beta[d0+j+1];
                uint32_t hh = pack_bf2(a0, a1);
                __nv_bfloat162 hv = *reinterpret_cast<__nv_bfloat162*>(&hh);
                *reinterpret_cast<uint32_t*>(&Kh[lr*LDQ + d0 + j]) = hh;
                *reinterpret_cast<uint32_t*>(&Kl[lr*LDQ + d0 + j]) =
                    pack_bf2(a0 - __bfloat162float(hv.x), a1 - __bfloat162float(hv.y));
            }
        }

        // ---- V tile: fp16 transpose into Vt[d][k] ----
        {
            union { uint4 u[4]; __half hh[32]; } vv;
            const uint4* vrow = reinterpret_cast<const uint4*>(Vp + (size_t)(k0 + lr)*HD + d0);
#pragma unroll
            for (int j = 0; j < 4; j++) vv.u[j] = vrow[j];
#pragma unroll
            for (int j = 0; j < 32; j++) Vt[(d0 + j)*LDV + lr] = vv.hh[j];
        }
        __syncthreads();

        // ---- S = Q*K^T : warp 16q x 128k via ldmatrix ----
        float S[16][4];
#pragma unroll
        for (int nf = 0; nf < 16; nf++)
#pragma unroll
            for (int t = 0; t < 4; t++) S[nf][t] = 0.0f;

#pragma unroll
        for (int ks = 0; ks < 4; ks++) {
            const uint32_t kb = ks * 16;
            uint32_t ah[4], al[4];
            const uint32_t qo = (aq_row * LDQ + kb + aq_col) * 2;
            ldsm4(ah, sb + OFF_QH + qo);
            ldsm4(al, sb + OFF_QL + qo);
#pragma unroll
            for (int p = 0; p < 8; p++) {
                const uint32_t ko = ((b_row + p*16) * LDQ + kb + b_col) * 2;
                uint32_t kh4[4], kl4[4];
                ldsm4(kh4, sb + OFF_KH + ko);
                ldsm4(kl4, sb + OFF_KL + ko);
                mma16816(S[2*p],   ah, kh4);
                mma16816(S[2*p],   ah, kl4);
                mma16816(S[2*p],   al, kh4);
                mma16816(S[2*p+1], ah, kh4 + 2);
                mma16816(S[2*p+1], ah, kl4 + 2);
                mma16816(S[2*p+1], al, kh4 + 2);
            }
        }

        // ---- mask + online softmax (rows wq+g, wq+g+8) ----
        {
            const unsigned char* m0p = mp + (size_t)(wq + g)*NUM_N + k0;
            const unsigned char* m1p = m0p + 8*NUM_N;
#pragma unroll
            for (int nf = 0; nf < 16; nf++) {
                const int cb = nf*8 + tg*2;
                uchar2 ma = *reinterpret_cast<const uchar2*>(m0p + cb);
                uchar2 mb = *reinterpret_cast<const uchar2*>(m1p + cb);
                if (ma.x) S[nf][0] = -3.402823466e38f;
                if (ma.y) S[nf][1] = -3.402823466e38f;
                if (mb.x) S[nf][2] = -3.402823466e38f;
                if (mb.y) S[nf][3] = -3.402823466e38f;
            }
            float rm0 = S[0][0], rm1 = S[0][2];
#pragma unroll
            for (int nf = 0; nf < 16; nf++) {
                rm0 = fmaxf(rm0, fmaxf(S[nf][0], S[nf][1]));
                rm1 = fmaxf(rm1, fmaxf(S[nf][2], S[nf][3]));
            }
            rm0 = fmaxf(rm0, __shfl_xor_sync(0xffffffffu, rm0, 1));
            rm0 = fmaxf(rm0, __shfl_xor_sync(0xffffffffu, rm0, 2));
            rm1 = fmaxf(rm1, __shfl_xor_sync(0xffffffffu, rm1, 1));
            rm1 = fmaxf(rm1, __shfl_xor_sync(0xffffffffu, rm1, 2));
            float mn0 = fmaxf(m_i[0], rm0);
            float mn1 = fmaxf(m_i[1], rm1);
            float al0 = __expf(m_i[0] - mn0);
            float al1 = __expf(m_i[1] - mn1);
            float ps0 = 0.f, ps1 = 0.f;
#pragma unroll
            for (int nf = 0; nf < 16; nf++) {
                S[nf][0] = __expf(S[nf][0] - mn0);
                S[nf][1] = __expf(S[nf][1] - mn0);
                S[nf][2] = __expf(S[nf][2] - mn1);
                S[nf][3] = __expf(S[nf][3] - mn1);
                ps0 += S[nf][0] + S[nf][1];
                ps1 += S[nf][2] + S[nf][3];
            }
            ps0 += __shfl_xor_sync(0xffffffffu, ps0, 1);
            ps0 += __shfl_xor_sync(0xffffffffu, ps0, 2);
            ps1 += __shfl_xor_sync(0xffffffffu, ps1, 1);
            ps1 += __shfl_xor_sync(0xffffffffu, ps1, 2);
            l_i[0] = l_i[0]*al0 + ps0;
            l_i[1] = l_i[1]*al1 + ps1;
            m_i[0] = mn0; m_i[1] = mn1;
#pragma unroll
            for (int dn = 0; dn < 8; dn++) {
                O[dn][0] *= al0; O[dn][1] *= al0;
                O[dn][2] *= al1; O[dn][3] *= al1;
            }
        }

        // ---- O += P*V : P from registers, V^T fp16 via ldmatrix ----
#pragma unroll
        for (int ks = 0; ks < 8; ks++) {
            uint32_t pa[4];
            pa[0] = pack_h2(S[2*ks  ][0], S[2*ks  ][1]);
            pa[1] = pack_h2(S[2*ks  ][2], S[2*ks  ][3]);
            pa[2] = pack_h2(S[2*ks+1][0], S[2*ks+1][1]);
            pa[3] = pack_h2(S[2*ks+1][2], S[2*ks+1][3]);
#pragma unroll
            for (int p = 0; p < 4; p++) {
                const uint32_t vo = ((b_row + p*16) * LDV + ks*16 + b_col) * 2;
                uint32_t vb[4];
                ldsm4(vb, sb + OFF_VT + vo);
                mma16816h(O[2*p],   pa, vb);
                mma16816h(O[2*p+1], pa, vb + 2);
            }
        }
    }

    // ---- epilogue: normalize + write bf16 hi/lo split directly ----
    {
        float inv0 = 1.0f / l_i[0];
        float inv1 = 1.0f / l_i[1];
        const size_t r0 = (size_t)(b*NUM_N + q0 + wq + g)     * NUM_C + h*HD;
        const size_t r1 = (size_t)(b*NUM_N + q0 + wq + g + 8) * NUM_C + h*HD;
#pragma unroll
        for (int dn = 0; dn < 8; dn++) {
            const int c = dn*8 + tg*2;
            {
                float o0 = O[dn][0]*inv0, o1 = O[dn][1]*inv0;
                uint32_t hh = pack_bf2(o0, o1);
                __nv_bfloat162 hv = *reinterpret_cast<__nv_bfloat162*>(&hh);
                *reinterpret_cast<uint32_t*>(&g_aoh[r0 + c]) = hh;
                *reinterpret_cast<uint32_t*>(&g_aol[r0 + c]) =
                    pack_bf2(o0 - __bfloat162float(hv.x), o1 - __bfloat162float(hv.y));
            }
            {
                float o0 = O[dn][2]*inv1, o1 = O[dn][3]*inv1;
                uint32_t hh = pack_bf2(o0, o1);
                __nv_bfloat162 hv = *reinterpret_cast<__nv_bfloat162*>(&hh);
                *reinterpret_cast<uint32_t*>(&g_aoh[r1 + c]) = hh;
                *reinterpret_cast<uint32_t*>(&g_aol[r1 + c]) =
                    pack_bf2(o0 - __bfloat162float(hv.x), o1 - __bfloat162float(hv.y));
            }
        }
    }
}

// ---------------------------------------------------------------------------
extern "C" void kernel_launch(void* const* d_in, const int* in_sizes, int n_in,
                              void* d_out, int out_size) {
    const float* x       = (const float*)d_in[0];
    const unsigned char* mask = (const unsigned char*)d_in[1];
    const float* w_qkv   = (const float*)d_in[2];
    const float* w_proj  = (const float*)d_in[3];
    const float* b_proj  = (const float*)d_in[4];
    const float* q_gamma = (const float*)d_in[5];
    const float* q_beta  = (const float*)d_in[6];
    const float* k_gamma = (const float*)d_in[7];
    const float* k_beta  = (const float*)d_in[8];
    float* out = (float*)d_out;

    cudaFuncSetAttribute(attn_kernel,  cudaFuncAttributeMaxDynamicSharedMemorySize, ATTN_SMEM);
    cudaFuncSetAttribute(mma_gemm<0>,  cudaFuncAttributeMaxDynamicSharedMemorySize, GEMM_SMEM);
    cudaFuncSetAttribute(mma_gemm<1>,  cudaFuncAttributeMaxDynamicSharedMemorySize, GEMM_SMEM);

    __nv_bfloat16 *xh, *xl, *wqh, *wql, *aoh, *aol, *wph, *wpl;
    cudaGetSymbolAddress((void**)&xh,  g_xh);  cudaGetSymbolAddress((void**)&xl,  g_xl);
    cudaGetSymbolAddress((void**)&wqh, g_wqh); cudaGetSymbolAddress((void**)&wql, g_wql);
    cudaGetSymbolAddress((void**)&aoh, g_aoh); cudaGetSymbolAddress((void**)&aol, g_aol);
    cudaGetSymbolAddress((void**)&wph, g_wph); cudaGetSymbolAddress((void**)&wpl, g_wpl);

    const int n4x  = MTOT*NUM_C/4;
    const int n4wq = 3*NUM_C*NUM_C/4;
    const int n4wp = NUM_C*NUM_C/4;
    split_conv<<<(n4x  + 255)/256, 256>>>(x,      xh,  xl,  n4x);
    split_conv<<<(n4wq + 255)/256, 256>>>(w_qkv,  wqh, wql, n4wq);
    split_conv<<<(n4wp + 255)/256, 256>>>(w_proj, wph, wpl, n4wp);

    // 1) QKV GEMM on tensor cores (q/k fp32, v fp16 epilogue)
    mma_gemm<0><<<dim3(3*NUM_C/128, MTOT/128), 256, GEMM_SMEM>>>(xh, xl, wqh, wql, nullptr, nullptr);

    // 2) tensor-core flash attention (fused LN, writes bf16 hi/lo ao)
    attn_kernel<<<dim3(NUM_N/128, NUM_B*NUM_H), 256, ATTN_SMEM>>>(
        mask, q_gamma, q_beta, k_gamma, k_beta);

    // 3) output projection on tensor cores (+bias)
    mma_gemm<1><<<dim3(NUM_C/128, MTOT/128), 256, GEMM_SMEM>>>(aoh, aol, wph, wpl, b_proj, out);
}

// round 16
// speedup vs baseline: 2.8947x; 1.0941x over previous
#include <cuda_runtime.h>
#include <cuda_bf16.h>
#include <cuda_fp16.h>
#include <math.h>
#include <cstdint>

#define NUM_B 2
#define NUM_N 2048
#define NUM_C 1024
#define NUM_H 16
#define HD    64
#define MTOT  (NUM_B*NUM_N)      /* 4096 */

// ---------------------------------------------------------------------------
// Scratch (allocation-free: __device__ globals)
// ---------------------------------------------------------------------------
__device__ __nv_bfloat16 g_qh[NUM_B*NUM_H*NUM_N*HD];  // LN'd q (x0.125) hi/lo
__device__ __nv_bfloat16 g_ql[NUM_B*NUM_H*NUM_N*HD];
__device__ __nv_bfloat16 g_kh[NUM_B*NUM_H*NUM_N*HD];  // LN'd k hi/lo
__device__ __nv_bfloat16 g_kl[NUM_B*NUM_H*NUM_N*HD];
__device__ __half        g_vh[NUM_B*NUM_H*NUM_N*HD];  // V fp16

// split-bf16 copies (hi/lo) for tensor-core GEMMs
__device__ __nv_bfloat16 g_xh [MTOT*NUM_C];
__device__ __nv_bfloat16 g_xl [MTOT*NUM_C];
__device__ __nv_bfloat16 g_wqh[3*NUM_C*NUM_C];
__device__ __nv_bfloat16 g_wql[3*NUM_C*NUM_C];
__device__ __nv_bfloat16 g_aoh[MTOT*NUM_C];    // attention out hi/lo
__device__ __nv_bfloat16 g_aol[MTOT*NUM_C];
__device__ __nv_bfloat16 g_wph[NUM_C*NUM_C];
__device__ __nv_bfloat16 g_wpl[NUM_C*NUM_C];

// ---------------------------------------------------------------------------
// PTX helpers
// ---------------------------------------------------------------------------
__device__ __forceinline__ uint32_t smem_to_u32(const void* p) {
    uint32_t a;
    asm("{ .reg .u64 t; cvta.to.shared.u64 t, %1; cvt.u32.u64 %0, t; }" : "=r"(a) : "l"(p));
    return a;
}
__device__ __forceinline__ void mma16816(float* d, const uint32_t* a, const uint32_t* b) {
    asm volatile(
        "mma.sync.aligned.m16n8k16.row.col.f32.bf16.bf16.f32 "
        "{%0,%1,%2,%3}, {%4,%5,%6,%7}, {%8,%9}, {%0,%1,%2,%3};"
        : "+f"(d[0]), "+f"(d[1]), "+f"(d[2]), "+f"(d[3])
        : "r"(a[0]), "r"(a[1]), "r"(a[2]), "r"(a[3]), "r"(b[0]), "r"(b[1]));
}
__device__ __forceinline__ void mma16816h(float* d, const uint32_t* a, const uint32_t* b) {
    asm volatile(
        "mma.sync.aligned.m16n8k16.row.col.f32.f16.f16.f32 "
        "{%0,%1,%2,%3}, {%4,%5,%6,%7}, {%8,%9}, {%0,%1,%2,%3};"
        : "+f"(d[0]), "+f"(d[1]), "+f"(d[2]), "+f"(d[3])
        : "r"(a[0]), "r"(a[1]), "r"(a[2]), "r"(a[3]), "r"(b[0]), "r"(b[1]));
}
__device__ __forceinline__ void ldsm4(uint32_t* r, uint32_t a) {
    asm volatile("ldmatrix.sync.aligned.m8n8.x4.shared.b16 {%0,%1,%2,%3}, [%4];"
        : "=r"(r[0]), "=r"(r[1]), "=r"(r[2]), "=r"(r[3]) : "r"(a));
}
__device__ __forceinline__ void ldsm4t(uint32_t* r, uint32_t a) {
    asm volatile("ldmatrix.sync.aligned.m8n8.x4.trans.shared.b16 {%0,%1,%2,%3}, [%4];"
        : "=r"(r[0]), "=r"(r[1]), "=r"(r[2]), "=r"(r[3]) : "r"(a));
}
#define CP16(dst, src) \
    asm volatile("cp.async.cg.shared.global [%0], [%1], 16;" :: "r"(dst), "l"(src))
#define CP_COMMIT() asm volatile("cp.async.commit_group;" ::: "memory")
#define CP_WAIT(n)  asm volatile("cp.async.wait_group %0;" :: "n"(n) : "memory")

__device__ __forceinline__ uint32_t pack_h2(float a, float b) {
    __half2 h = __floats2half2_rn(a, b);
    return *reinterpret_cast<uint32_t*>(&h);
}
__device__ __forceinline__ uint32_t pack_bf2(float a, float b) {
    __nv_bfloat162 h(__float2bfloat16(a), __float2bfloat16(b));
    return *reinterpret_cast<uint32_t*>(&h);
}
// swizzled byte offset within a 128-row x 128B tile
__device__ __forceinline__ uint32_t swz(uint32_t row, uint32_t chunk) {
    return row * 128u + ((chunk ^ (row & 7u)) * 16u);
}

// ---------------------------------------------------------------------------
// Kernel 0: fp32 -> (bf16 hi, bf16 lo) split conversion, 4 elems/thread.
// ---------------------------------------------------------------------------
struct __align__(8) bf4 { __nv_bfloat16 a, b, c, d; };

__global__ __launch_bounds__(256) void split_conv(const float* __restrict__ s,
                                                  __nv_bfloat16* __restrict__ hi,
                                                  __nv_bfloat16* __restrict__ lo,
                                                  int n4) {
    int i = blockIdx.x * blockDim.x + threadIdx.x;
    if (i >= n4) return;
    float4 v = reinterpret_cast<const float4*>(s)[i];
    __nv_bfloat16 h0 = __float2bfloat16(v.x);
    __nv_bfloat16 h1 = __float2bfloat16(v.y);
    __nv_bfloat16 h2 = __float2bfloat16(v.z);
    __nv_bfloat16 h3 = __float2bfloat16(v.w);
    __nv_bfloat16 l0 = __float2bfloat16(v.x - __bfloat162float(h0));
    __nv_bfloat16 l1 = __float2bfloat16(v.y - __bfloat162float(h1));
    __nv_bfloat16 l2 = __float2bfloat16(v.z - __bfloat162float(h2));
    __nv_bfloat16 l3 = __float2bfloat16(v.w - __bfloat162float(h3));
    bf4 hh = {h0, h1, h2, h3};
    bf4 ll = {l0, l1, l2, l3};
    reinterpret_cast<bf4*>(hi)[i] = hh;
    reinterpret_cast<bf4*>(lo)[i] = ll;
}

// ---------------------------------------------------------------------------
// Kernel 1/3: mma.sync bf16-split GEMM.  Block 128x128, BK=32, 8 warps.
// cp.async double-buffer + ldmatrix.  2 CTAs/SM.
// EPI=0: q/k rows LayerNormed in-epilogue -> bf16 hi/lo; v -> fp16.
// EPI=1: out + bias.
// ---------------------------------------------------------------------------
#define LDA 40
#define ARR_B   (128*LDA*2)
#define STAGE_B (4*ARR_B)
#define GEMM_SMEM (2*STAGE_B)

template<int EPI>
__global__ __launch_bounds__(256, 2) void mma_gemm(const __nv_bfloat16* __restrict__ Ah,
                                                   const __nv_bfloat16* __restrict__ Al,
                                                   const __nv_bfloat16* __restrict__ Bh,
                                                   const __nv_bfloat16* __restrict__ Bl,
                                                   const float* __restrict__ bias,
                                                   float* __restrict__ outp,
                                                   const float* __restrict__ q_gamma,
                                                   const float* __restrict__ q_beta,
                                                   const float* __restrict__ k_gamma,
                                                   const float* __restrict__ k_beta) {
    extern __shared__ __nv_bfloat16 smem[];
    const uint32_t sb = smem_to_u32(smem);
    const int tid  = threadIdx.x;
    const int wid  = tid >> 5, lane = tid & 31;
    const int wm   = wid >> 1;
    const int wn   = wid & 1;
    const int g    = lane >> 2;
    const int tg   = lane & 3;
    const int bm   = blockIdx.y * 128;
    const int bn   = blockIdx.x * 128;

    const int lrow  = tid >> 1;
    const int lhalf = (tid & 1) * 16;
    const __nv_bfloat16* gah = Ah + (size_t)(bm + lrow) * NUM_C + lhalf;
    const __nv_bfloat16* gal = Al + (size_t)(bm + lrow) * NUM_C + lhalf;
    const __nv_bfloat16* gbh = Bh + (size_t)(bn + lrow) * NUM_C + lhalf;
    const __nv_bfloat16* gbl = Bl + (size_t)(bn + lrow) * NUM_C + lhalf;
    const uint32_t dstA = sb + (uint32_t)(lrow * LDA + lhalf) * 2;

#define GISSUE(s, c) do {                                                      \
        uint32_t _d = dstA + (uint32_t)(s) * STAGE_B;                          \
        const int _go = (c) * 32;                                              \
        CP16(_d,               gah + _go); CP16(_d + 16,           gah + _go + 8); \
        CP16(_d +   ARR_B,     gal + _go); CP16(_d +   ARR_B + 16, gal + _go + 8); \
        CP16(_d + 2*ARR_B,     gbh + _go); CP16(_d + 2*ARR_B + 16, gbh + _go + 8); \
        CP16(_d + 3*ARR_B,     gbl + _go); CP16(_d + 3*ARR_B + 16, gbl + _go + 8); \
    } while (0)

    const uint32_t arow = (uint32_t)(wm*32 + ((lane>>3)&1)*8 + (lane&7));
    const uint32_t acol = (uint32_t)((lane>>4)*8);
    const uint32_t brow = (uint32_t)(wn*64 + ((lane>>4)&1)*8 + (lane&7));
    const uint32_t bcol = (uint32_t)(((lane>>3)&1)*8);

    float acc[2][8][4];
#pragma unroll
    for (int i = 0; i < 2; i++)
#pragma unroll
        for (int j = 0; j < 8; j++)
#pragma unroll
            for (int t = 0; t < 4; t++) acc[i][j][t] = 0.0f;

    GISSUE(0, 0);
    CP_COMMIT();

    for (int c = 0; c < NUM_C/32; c++) {
        if (c + 1 < NUM_C/32) {
            GISSUE((c + 1) & 1, c + 1);
            CP_COMMIT();
            CP_WAIT(1);
        } else {
            CP_WAIT(0);
        }
        __syncthreads();

        const uint32_t stB = sb + (uint32_t)(c & 1) * STAGE_B;
#pragma unroll
        for (int ks = 0; ks < 2; ks++) {
            const uint32_t kb = ks * 16;
            uint32_t fah[2][4], fal[2][4];
#pragma unroll
            for (int mf = 0; mf < 2; mf++) {
                const uint32_t ao = ((arow + mf*16) * LDA + kb + acol) * 2;
                ldsm4(fah[mf], stB + ao);
                ldsm4(fal[mf], stB + ARR_B + ao);
            }
#pragma unroll
            for (int p = 0; p < 4; p++) {
                const uint32_t bo = ((brow + p*16) * LDA + kb + bcol) * 2;
                uint32_t bh4[4], bl4[4];
                ldsm4(bh4, stB + 2*ARR_B + bo);
                ldsm4(bl4, stB + 3*ARR_B + bo);
#pragma unroll
                for (int mf = 0; mf < 2; mf++) {
                    mma16816(acc[mf][2*p],   fah[mf], bh4);
                    mma16816(acc[mf][2*p],   fah[mf], bl4);
                    mma16816(acc[mf][2*p],   fal[mf], bh4);
                    mma16816(acc[mf][2*p+1], fah[mf], bh4 + 2);
                    mma16816(acc[mf][2*p+1], fah[mf], bl4 + 2);
                    mma16816(acc[mf][2*p+1], fal[mf], bh4 + 2);
                }
            }
        }
        __syncthreads();
    }
#undef GISSUE

    if (EPI == 0) {
        const int n0 = bn + wn*64;
        const int which = n0 >> 10;
        const int h = (n0 & 1023) >> 6;
        if (which < 2) {
            // fused LayerNorm over the 64-col head row (held by the tg-quad)
            __nv_bfloat16* dh = (which == 0) ? g_qh : g_kh;
            __nv_bfloat16* dl = (which == 0) ? g_ql : g_kl;
            const float* gam = (which == 0) ? q_gamma : k_gamma;
            const float* bet = (which == 0) ? q_beta  : k_beta;
            const float scl = (which == 0) ? 0.125f : 1.0f;
            float gv[16], bv[16];
#pragma unroll
            for (int nf = 0; nf < 8; nf++) {
                float2 g2 = *reinterpret_cast<const float2*>(&gam[nf*8 + tg*2]);
                float2 b2 = *reinterpret_cast<const float2*>(&bet[nf*8 + tg*2]);
                gv[2*nf] = g2.x; gv[2*nf+1] = g2.y;
                bv[2*nf] = b2.x * scl; bv[2*nf+1] = b2.y * scl;
            }
#pragma unroll
            for (int mf = 0; mf < 2; mf++) {
#pragma unroll
                for (int half = 0; half < 2; half++) {
                    float s = 0.f, ss = 0.f;
#pragma unroll
                    for (int nf = 0; nf < 8; nf++) {
                        float v0 = acc[mf][nf][half*2], v1 = acc[mf][nf][half*2+1];
                        s += v0 + v1; ss += v0*v0 + v1*v1;
                    }
                    s  += __shfl_xor_sync(0xffffffffu, s,  1);
                    s  += __shfl_xor_sync(0xffffffffu, s,  2);
                    ss += __shfl_xor_sync(0xffffffffu, ss, 1);
                    ss += __shfl_xor_sync(0xffffffffu, ss, 2);
                    float mu  = s * (1.0f/64.0f);
                    float var = ss * (1.0f/64.0f) - mu*mu;
                    float inv = rsqrtf(var + 1e-5f) * scl;
                    const int mrow = bm + wm*32 + mf*16 + g + half*8;
                    const size_t rb = (((size_t)((mrow >> 11) * NUM_H + h)) * NUM_N
                                       + (mrow & 2047)) * HD;
#pragma unroll
                    for (int nf = 0; nf < 8; nf++) {
                        float a0 = (acc[mf][nf][half*2]   - mu)*inv*gv[2*nf]   + bv[2*nf];
                        float a1 = (acc[mf][nf][half*2+1] - mu)*inv*gv[2*nf+1] + bv[2*nf+1];
                        uint32_t hh = pack_bf2(a0, a1);
                        __nv_bfloat162 hv = *reinterpret_cast<__nv_bfloat162*>(&hh);
                        *reinterpret_cast<uint32_t*>(&dh[rb + nf*8 + tg*2]) = hh;
                        *reinterpret_cast<uint32_t*>(&dl[rb + nf*8 + tg*2]) =
                            pack_bf2(a0 - __bfloat162float(hv.x), a1 - __bfloat162float(hv.y));
                    }
                }
            }
        } else {
#pragma unroll
            for (int mf = 0; mf < 2; mf++) {
#pragma unroll
                for (int half = 0; half < 2; half++) {
                    const int mrow = bm + wm*32 + mf*16 + g + half*8;
                    __half* dst = g_vh + (((size_t)((mrow >> 11) * NUM_H + h)) * NUM_N
                                          + (mrow & 2047)) * HD;
#pragma unroll
                    for (int nf = 0; nf < 8; nf++) {
                        *reinterpret_cast<uint32_t*>(dst + nf*8 + tg*2) =
                            pack_h2(acc[mf][nf][half*2], acc[mf][nf][half*2+1]);
                    }
                }
            }
        }
    } else {
#pragma unroll
        for (int mf = 0; mf < 2; mf++) {
#pragma unroll
            for (int half = 0; half < 2; half++) {
                const int mrow = bm + wm*32 + mf*16 + g + half*8;
                float* dst = outp + (size_t)mrow * NUM_C + bn + wn*64;
#pragma unroll
                for (int nf = 0; nf < 8; nf++) {
                    const int col = bn + wn*64 + nf*8 + tg*2;
                    *reinterpret_cast<float2*>(dst + nf*8 + tg*2) =
                        make_float2(acc[mf][nf][half*2] + bias[col],
                                    acc[mf][nf][half*2+1] + bias[col+1]);
                }
            }
        }
    }
}

// ---------------------------------------------------------------------------
// Kernel 2: tensor-core flash attention.  Inputs already LN'd bf16 hi/lo.
// Block = 128 q of one (b,h), 8 warps, warp tile 16q x 128k.
// cp.async double-buffered K/V stages; swizzled 64-col tiles; V via
// ldmatrix.trans (no explicit transpose).  Writes bf16 hi/lo ao.
// ---------------------------------------------------------------------------
#define TILE_B   16384                     /* 128 rows x 128 B */
#define OFF_QH   0
#define OFF_QL   TILE_B
#define OFF_ST(s) (2*TILE_B + (s)*(3*TILE_B))   /* KH, KL, V per stage */
#define ATTN_SMEM (2*TILE_B + 2*3*TILE_B)  /* 131072 B */

__global__ __launch_bounds__(256) void attn_kernel(const unsigned char* __restrict__ mask) {
    extern __shared__ char asmem[];
    const uint32_t sb = smem_to_u32(asmem);

    const int bh = blockIdx.y;
    const int b  = bh >> 4;
    const int h  = bh & 15;
    const int q0 = blockIdx.x * 128;

    const __nv_bfloat16* Qhg = g_qh + ((size_t)bh*NUM_N + q0)*HD;
    const __nv_bfloat16* Qlg = g_ql + ((size_t)bh*NUM_N + q0)*HD;
    const __nv_bfloat16* Khg = g_kh + (size_t)bh*NUM_N*HD;
    const __nv_bfloat16* Klg = g_kl + (size_t)bh*NUM_N*HD;
    const __half*        Vg  = g_vh + (size_t)bh*NUM_N*HD;
    const unsigned char* mp  = mask + (size_t)b*NUM_N*NUM_N + (size_t)q0*NUM_N;

    const int tid  = threadIdx.x;
    const int wid  = tid >> 5, lane = tid & 31;
    const int g    = lane >> 2;
    const int tg   = lane & 3;
    const int wq   = wid * 16;

    // loader mapping: row = tid>>1, 4 chunks of 16B
    const uint32_t lrow = (uint32_t)(tid >> 1);
    const uint32_t lch0 = (uint32_t)((tid & 1) * 4);

    // fragment lane addressing (logical row/chunk; swizzle applied at use)
    const uint32_t aq_row = (uint32_t)(wq + ((lane>>3)&1)*8 + (lane&7));
    const uint32_t aq_ch  = (uint32_t)(lane>>4);            // + 2*ks
    const uint32_t kn_row = (uint32_t)(((lane>>4)&1)*8 + (lane&7));  // + 16*p
    const uint32_t kn_ch  = (uint32_t)((lane>>3)&1);        // + 2*ks
    const uint32_t v_row  = (uint32_t)(((lane>>3)&1)*8 + (lane&7));  // + 16*ks
    const uint32_t v_ch   = (uint32_t)(lane>>4);            // + 2*p

    // ---- prologue: Q hi/lo + stage 0 ----
#pragma unroll
    for (int j = 0; j < 4; j++) {
        const uint32_t ch = lch0 + j;
        const uint32_t so = swz(lrow, ch);
        CP16(sb + OFF_QH + so, Qhg + lrow*HD + ch*8);
        CP16(sb + OFF_QL + so, Qlg + lrow*HD + ch*8);
    }
#define KVISSUE(s, kt) do {                                                    \
        const uint32_t _st = OFF_ST(s);                                        \
        const int _k0 = (kt) * 128;                                            \
        _Pragma("unroll")                                                      \
        for (int j = 0; j < 4; j++) {                                          \
            const uint32_t ch = lch0 + j;                                      \
            const uint32_t so = swz(lrow, ch);                                 \
            CP16(sb + _st + so,            Khg + (size_t)(_k0 + lrow)*HD + ch*8); \
            CP16(sb + _st + TILE_B + so,   Klg + (size_t)(_k0 + lrow)*HD + ch*8); \
            CP16(sb + _st + 2*TILE_B + so, Vg  + (size_t)(_k0 + lrow)*HD + ch*8); \
        }                                                                      \
    } while (0)
    KVISSUE(0, 0);
    CP_COMMIT();

    float m_i[2], l_i[2];
    float O[8][4];
    m_i[0] = m_i[1] = -3.402823466e38f;
    l_i[0] = l_i[1] = 0.0f;
#pragma unroll
    for (int dn = 0; dn < 8; dn++)
#pragma unroll
        for (int t = 0; t < 4; t++) O[dn][t] = 0.0f;

    for (int kt = 0; kt < NUM_N/128; kt++) {
        const int k0 = kt * 128;
        if (kt + 1 < NUM_N/128) {
            KVISSUE((kt + 1) & 1, kt + 1);
            CP_COMMIT();
            CP_WAIT(1);
        } else {
            CP_WAIT(0);
        }
        __syncthreads();
        const uint32_t st = OFF_ST(kt & 1);

        // ---- S = Q*K^T : 3-term bf16 split via ldmatrix ----
        float S[16][4];
#pragma unroll
        for (int nf = 0; nf < 16; nf++)
#pragma unroll
            for (int t = 0; t < 4; t++) S[nf][t] = 0.0f;

#pragma unroll
        for (int ks = 0; ks < 4; ks++) {
            uint32_t ah[4], al[4];
            const uint32_t qo = swz(aq_row, 2*ks + aq_ch);
            ldsm4(ah, sb + OFF_QH + qo);
            ldsm4(al, sb + OFF_QL + qo);
#pragma unroll
            for (int p = 0; p < 8; p++) {
                const uint32_t ko = swz(kn_row + p*16, 2*ks + kn_ch);
                uint32_t kh4[4], kl4[4];
                ldsm4(kh4, sb + st + ko);
                ldsm4(kl4, sb + st + TILE_B + ko);
                mma16816(S[2*p],   ah, kh4);
                mma16816(S[2*p],   ah, kl4);
                mma16816(S[2*p],   al, kh4);
                mma16816(S[2*p+1], ah, kh4 + 2);
                mma16816(S[2*p+1], ah, kl4 + 2);
                mma16816(S[2*p+1], al, kh4 + 2);
            }
        }

        // ---- mask + online softmax (rows wq+g, wq+g+8) ----
        {
            const unsigned char* m0p = mp + (size_t)(wq + g)*NUM_N + k0;
            const unsigned char* m1p = m0p + 8*NUM_N;
#pragma unroll
            for (int nf = 0; nf < 16; nf++) {
                const int cb = nf*8 + tg*2;
                uchar2 ma = *reinterpret_cast<const uchar2*>(m0p + cb);
                uchar2 mb = *reinterpret_cast<const uchar2*>(m1p + cb);
                if (ma.x) S[nf][0] = -3.402823466e38f;
                if (ma.y) S[nf][1] = -3.402823466e38f;
                if (mb.x) S[nf][2] = -3.402823466e38f;
                if (mb.y) S[nf][3] = -3.402823466e38f;
            }
            float rm0 = S[0][0], rm1 = S[0][2];
#pragma unroll
            for (int nf = 0; nf < 16; nf++) {
                rm0 = fmaxf(rm0, fmaxf(S[nf][0], S[nf][1]));
                rm1 = fmaxf(rm1, fmaxf(S[nf][2], S[nf][3]));
            }
            rm0 = fmaxf(rm0, __shfl_xor_sync(0xffffffffu, rm0, 1));
            rm0 = fmaxf(rm0, __shfl_xor_sync(0xffffffffu, rm0, 2));
            rm1 = fmaxf(rm1, __shfl_xor_sync(0xffffffffu, rm1, 1));
            rm1 = fmaxf(rm1, __shfl_xor_sync(0xffffffffu, rm1, 2));
            float mn0 = fmaxf(m_i[0], rm0);
            float mn1 = fmaxf(m_i[1], rm1);
            float al0 = __expf(m_i[0] - mn0);
            float al1 = __expf(m_i[1] - mn1);
            float ps0 = 0.f, ps1 = 0.f;
#pragma unroll
            for (int nf = 0; nf < 16; nf++) {
                S[nf][0] = __expf(S[nf][0] - mn0);
                S[nf][1] = __expf(S[nf][1] - mn0);
                S[nf][2] = __expf(S[nf][2] - mn1);
                S[nf][3] = __expf(S[nf][3] - mn1);
                ps0 += S[nf][0] + S[nf][1];
                ps1 += S[nf][2] + S[nf][3];
            }
            ps0 += __shfl_xor_sync(0xffffffffu, ps0, 1);
            ps0 += __shfl_xor_sync(0xffffffffu, ps0, 2);
            ps1 += __shfl_xor_sync(0xffffffffu, ps1, 1);
            ps1 += __shfl_xor_sync(0xffffffffu, ps1, 2);
            l_i[0] = l_i[0]*al0 + ps0;
            l_i[1] = l_i[1]*al1 + ps1;
            m_i[0] = mn0; m_i[1] = mn1;
#pragma unroll
            for (int dn = 0; dn < 8; dn++) {
                O[dn][0] *= al0; O[dn][1] *= al0;
                O[dn][2] *= al1; O[dn][3] *= al1;
            }
        }

        // ---- O += P*V : P from registers, V natural [k][d] via ldsm.trans ----
#pragma unroll
        for (int ks = 0; ks < 8; ks++) {
            uint32_t pa[4];
            pa[0] = pack_h2(S[2*ks  ][0], S[2*ks  ][1]);
            pa[1] = pack_h2(S[2*ks  ][2], S[2*ks  ][3]);
            pa[2] = pack_h2(S[2*ks+1][0], S[2*ks+1][1]);
            pa[3] = pack_h2(S[2*ks+1][2], S[2*ks+1][3]);
#pragma unroll
            for (int p = 0; p < 4; p++) {
                const uint32_t vo = swz(ks*16 + v_row, p*2 + v_ch);
                uint32_t vb[4];
                ldsm4t(vb, sb + st + 2*TILE_B + vo);
                mma16816h(O[2*p],   pa, vb);
                mma16816h(O[2*p+1], pa, vb + 2);
            }
        }
        __syncthreads();   // all reads of stage (kt&1) done before reuse
    }
#undef KVISSUE

    // ---- epilogue: normalize + write bf16 hi/lo split ----
    {
        float inv0 = 1.0f / l_i[0];
        float inv1 = 1.0f / l_i[1];
        const size_t r0 = (size_t)(b*NUM_N + q0 + wq + g)     * NUM_C + h*HD;
        const size_t r1 = (size_t)(b*NUM_N + q0 + wq + g + 8) * NUM_C + h*HD;
#pragma unroll
        for (int dn = 0; dn < 8; dn++) {
            const int c = dn*8 + tg*2;
            {
                float o0 = O[dn][0]*inv0, o1 = O[dn][1]*inv0;
                uint32_t hh = pack_bf2(o0, o1);
                __nv_bfloat162 hv = *reinterpret_cast<__nv_bfloat162*>(&hh);
                *reinterpret_cast<uint32_t*>(&g_aoh[r0 + c]) = hh;
                *reinterpret_cast<uint32_t*>(&g_aol[r0 + c]) =
                    pack_bf2(o0 - __bfloat162float(hv.x), o1 - __bfloat162float(hv.y));
            }
            {
                float o0 = O[dn][2]*inv1, o1 = O[dn][3]*inv1;
                uint32_t hh = pack_bf2(o0, o1);
                __nv_bfloat162 hv = *reinterpret_cast<__nv_bfloat162*>(&hh);
                *reinterpret_cast<uint32_t*>(&g_aoh[r1 + c]) = hh;
                *reinterpret_cast<uint32_t*>(&g_aol[r1 + c]) =
                    pack_bf2(o0 - __bfloat162float(hv.x), o1 - __bfloat162float(hv.y));
            }
        }
    }
}

// ---------------------------------------------------------------------------
extern "C" void kernel_launch(void* const* d_in, const int* in_sizes, int n_in,
                              void* d_out, int out_size) {
    const float* x       = (const float*)d_in[0];
    const unsigned char* mask = (const unsigned char*)d_in[1];
    const float* w_qkv   = (const float*)d_in[2];
    const float* w_proj  = (const float*)d_in[3];
    const float* b_proj  = (const float*)d_in[4];
    const float* q_gamma = (const float*)d_in[5];
    const float* q_beta  = (const float*)d_in[6];
    const float* k_gamma = (const float*)d_in[7];
    const float* k_beta  = (const float*)d_in[8];
    float* out = (float*)d_out;

    cudaFuncSetAttribute(attn_kernel,  cudaFuncAttributeMaxDynamicSharedMemorySize, ATTN_SMEM);
    cudaFuncSetAttribute(mma_gemm<0>,  cudaFuncAttributeMaxDynamicSharedMemorySize, GEMM_SMEM);
    cudaFuncSetAttribute(mma_gemm<1>,  cudaFuncAttributeMaxDynamicSharedMemorySize, GEMM_SMEM);

    __nv_bfloat16 *xh, *xl, *wqh, *wql, *aoh, *aol, *wph, *wpl;
    cudaGetSymbolAddress((void**)&xh,  g_xh);  cudaGetSymbolAddress((void**)&xl,  g_xl);
    cudaGetSymbolAddress((void**)&wqh, g_wqh); cudaGetSymbolAddress((void**)&wql, g_wql);
    cudaGetSymbolAddress((void**)&aoh, g_aoh); cudaGetSymbolAddress((void**)&aol, g_aol);
    cudaGetSymbolAddress((void**)&wph, g_wph); cudaGetSymbolAddress((void**)&wpl, g_wpl);

    const int n4x  = MTOT*NUM_C/4;
    const int n4wq = 3*NUM_C*NUM_C/4;
    const int n4wp = NUM_C*NUM_C/4;
    split_conv<<<(n4x  + 255)/256, 256>>>(x,      xh,  xl,  n4x);
    split_conv<<<(n4wq + 255)/256, 256>>>(w_qkv,  wqh, wql, n4wq);
    split_conv<<<(n4wp + 255)/256, 256>>>(w_proj, wph, wpl, n4wp);

    // 1) QKV GEMM (fused q/k LayerNorm -> bf16 hi/lo; v -> fp16)
    mma_gemm<0><<<dim3(3*NUM_C/128, MTOT/128), 256, GEMM_SMEM>>>(
        xh, xl, wqh, wql, nullptr, nullptr, q_gamma, q_beta, k_gamma, k_beta);

    // 2) tensor-core flash attention (writes bf16 hi/lo ao)
    attn_kernel<<<dim3(NUM_N/128, NUM_B*NUM_H), 256, ATTN_SMEM>>>(mask);

    // 3) output projection (+bias)
    mma_gemm<1><<<dim3(NUM_C/128, MTOT/128), 256, GEMM_SMEM>>>(
        aoh, aol, wph, wpl, b_proj, out, nullptr, nullptr, nullptr, nullptr);
}